// round 6
// baseline (speedup 1.0000x reference)
#include <cuda_runtime.h>
#include <cuda_bf16.h>
#include <math.h>

typedef unsigned long long ull;

// Shapes
#define Bsz   32
#define Ndim  64
#define Hdim  256
#define INTER 912      // 2H + 6C + C1
#define TSTEP 64
#define SEQPB 28       // sequences per gru2d block
#define NBLK2 147      // ceil(4096/28) -> exactly one wave on 148 SMs

// f32x2 packed helpers (sm_100+ PTX; ptxas won't auto-fuse)
#define FFMA2(acc, a, b)   asm("fma.rn.f32x2 %0, %1, %2, %0;" : "+l"(acc) : "l"(a), "l"(b))
#define ADD2(d, a, b)      asm("add.rn.f32x2 %0, %1, %2;" : "=l"(d) : "l"(a), "l"(b))
#define PACK1(d, s)        asm("mov.b64 %0, {%1, %1};" : "=l"(d) : "f"(s))
#define PACKAB(d, lo, hi)  asm("mov.b64 %0, {%1, %2;}" : "=l"(d) : "f"(lo), "f"(hi))
#undef PACKAB
#define PACKAB(d, lo, hi)  asm("mov.b64 %0, {%1, %2};" : "=l"(d) : "f"(lo), "f"(hi))
#define UNPACK2(lo, hi, s) asm("mov.b64 {%0, %1}, %2;" : "=f"(lo), "=f"(hi) : "l"(s))

// ---------------- scratch (device globals; no cudaMalloc allowed) ----------------
__device__ float d_f[Bsz * Ndim * INTER];        // fused feature tensor [B,N,912]
__device__ float d_xW1[Bsz * Ndim * 768];        // precomputed f @ Wih1^T + bih1
__device__ float d_W2p[80 * 768 * 4];            // gru2d packed: [k/4][g*256+o][kk]; chunks 0..63=Whh, 64..79=Wih
__device__ float d_WhT1[256 * 768];              // gru1d Whh transposed [k][o]
__device__ float d_WiT1[912 * 768];              // gru1d Wih transposed
__device__ float d_fc1WT[2992 * 256];            // fc1 W transposed [j][o]
__device__ float d_hlast[Bsz * Hdim];
__device__ int   d_perm_is32;

__device__ __forceinline__ float sigm(float x) { return 1.f / (1.f + __expf(-x)); }

// ---------------- perm dtype probe (int64 vs int32) ----------------
__global__ void detect_kernel(const long long* __restrict__ p) {
    if (threadIdx.x == 0 && blockIdx.x == 0) {
        int is32 = 0;
        for (int i = 0; i < 32; ++i) {
            long long v = p[i];
            if (v < 0 || v >= 64) is32 = 1;   // int32 data read as int64 overflows range
        }
        d_perm_is32 = is32;
    }
}

// ---------------- weight transposes / packing ----------------
// segments: W2p(245760) WhT1(196608) WiT1(700416) fc1WT(765952) -> 1908736
__global__ void prep_kernel(const float* __restrict__ Whh2, const float* __restrict__ Wih2,
                            const float* __restrict__ Whh1, const float* __restrict__ Wih1,
                            const float* __restrict__ fc1W) {
    int i = blockIdx.x * blockDim.x + threadIdx.x;
    if (i < 245760) {
        int c = i / 3072;           // chunk stride = 768*4 = 3072 floats
        int rem = i % 3072;
        int o = rem >> 2, kk = rem & 3;   // o = g*256 + out-channel (0..767)
        if (c < 64) d_W2p[i] = Whh2[o * 256 + (4 * c + kk)];
        else        d_W2p[i] = Wih2[o * 64 + (4 * (c - 64) + kk)];
    } else if (i < 442368) {
        int j = i - 245760; int k = j / 768, o = j % 768;
        d_WhT1[j] = Whh1[o * 256 + k];
    } else if (i < 1142784) {
        int j = i - 442368; int k = j / 768, o = j % 768;
        d_WiT1[j] = Wih1[o * 912 + k];
    } else if (i < 1908736) {
        int j = i - 1142784; int o = j % 256, j2 = j / 256;
        d_fc1WT[j] = fc1W[o * 2992 + j2];
    }
}

// ---------------- pools over states + x1 copy into f ----------------
__global__ void pool_kernel(const float* __restrict__ states, const float* __restrict__ x1) {
    int i = blockIdx.x * blockDim.x + threadIdx.x;
    if (i < 131072) {
        int c = i & 63, j = (i >> 6) & 63, b = i >> 12;
        float mx = -1e30f, mn = 1e30f, sm = 0.f;
        for (int n = 0; n < 64; ++n) {
            float v = states[(((b * 64 + n) * 64 + j) << 6) + c];
            mx = fmaxf(mx, v); mn = fminf(mn, v); sm += v;
        }
        float* fp = d_f + (size_t)(b * 64 + j) * INTER;
        fp[16 + c] = mx; fp[80 + c] = sm * (1.f / 64.f); fp[144 + c] = mn;
    } else if (i < 262144) {
        int i2 = i - 131072;
        int c = i2 & 63, n = (i2 >> 6) & 63, b = i2 >> 12;
        float mx = -1e30f, mn = 1e30f, sm = 0.f;
        const float* row = states + (((size_t)(b * 64 + n) * 64) << 6) + c;
        for (int m = 0; m < 64; ++m) {
            float v = row[m << 6];
            mx = fmaxf(mx, v); mn = fminf(mn, v); sm += v;
        }
        float* fp = d_f + (size_t)(b * 64 + n) * INTER;
        fp[208 + c] = mx; fp[272 + c] = sm * (1.f / 64.f); fp[336 + c] = mn;
    } else if (i < 294912) {
        int i3 = i - 262144;
        d_f[(size_t)(i3 >> 4) * INTER + (i3 & 15)] = x1[i3];
    }
}

// ---------------- gather helper for gru2d ----------------
__device__ __forceinline__ float gather_one(const float* __restrict__ states, int seq0, int i, int tt,
        int is32, const int* __restrict__ p1_32, const long long* __restrict__ p1_64,
        const int* __restrict__ p2_32, const long long* __restrict__ p2_64) {
    int si = i >> 6, c = i & 63, s = seq0 + si;
    if (s >= 4096) return 0.f;
    const float* src;
    if (s < 2048) {
        int b = s >> 6, n = s & 63;
        int m = is32 ? p1_32[n * 64 + tt] : (int)p1_64[n * 64 + tt];
        src = states + (((size_t)((b * 64 + n) * 64 + m)) << 6);
    } else {
        int sp = s - 2048;
        int b = sp >> 6, n = sp & 63;
        int sn = is32 ? p2_32[n * 64 + tt] : (int)p2_64[n * 64 + tt];
        src = states + (((size_t)((b * 64 + sn) * 64 + n)) << 6);
    }
    return __ldg(src + c);
}

// SMEM layout (floats):
//   hT   [256][28]        @ 0       (7168)
//   xT   [2][64][28]      @ 7168    (3584)
//   rbuf [256][30]        @ 10752   (7680)
//   zbuf [256][30]        @ 18432   (7680)
//   nbuf [256][30]        @ 26112   (7680)
//   total 33792 floats = 135168 bytes (dynamic smem)
#define SM_HT   0
#define SM_XT   7168
#define SM_RB   10752
#define SM_ZB   18432
#define SM_NB   26112
#define SM_TOTF 33792

// ---------------- fused 2D GRU: 4096 seqs, 28/block, 147 blocks, 768 threads ----------------
// thread tid = g*256 + ch owns ONE (gate, channel) output across 28 sequences.
__global__ void __launch_bounds__(768, 1) gru2d_kernel(
    const float* __restrict__ states,
    const void* __restrict__ perm1v, const void* __restrict__ perm2v,
    const float* __restrict__ bih, const float* __restrict__ bhh) {
    extern __shared__ float smf[];
    float* hTf = smf + SM_HT;
    float* xTf = smf + SM_XT;
    float* rbuf = smf + SM_RB;
    float* zbuf = smf + SM_ZB;
    float* nbuf = smf + SM_NB;

    const int tid = threadIdx.x;
    const int g   = tid >> 8;       // 0=r, 1=z, 2=n
    const int ch  = tid & 255;
    const int seq0 = blockIdx.x * SEQPB;
    const int is32 = d_perm_is32;
    const long long* __restrict__ p1_64 = (const long long*)perm1v;
    const long long* __restrict__ p2_64 = (const long long*)perm2v;
    const int* __restrict__ p1_32 = (const int*)perm1v;
    const int* __restrict__ p2_32 = (const int*)perm2v;
    const float4* __restrict__ Wp4 = (const float4*)d_W2p;

    // biases: g<2: full bias; g==2: b_in = bih, b_hn = bhh (kept separate)
    const float bmain = bih[tid] + ((g < 2) ? bhh[tid] : 0.f);
    const float bhn   = bhh[tid];

    // init h = 0
    for (int u = tid; u < 7168; u += 768) hTf[u] = 0.f;
    // initial gather (t=0)
    for (int u = tid; u < SEQPB * 64; u += 768) {
        float v = gather_one(states, seq0, u, 0, is32, p1_32, p1_64, p2_32, p2_64);
        xTf[(u & 63) * 28 + (u >> 6)] = v;
    }
    __syncthreads();

    int cur = 0;
    for (int t = 0; t < TSTEP; ++t) {
        // prefetch next step's x early (long-latency LDGs covered by mainloop)
        float px0 = 0.f, px1 = 0.f, px2 = 0.f;
        if (t < TSTEP - 1) {
            px0 = gather_one(states, seq0, tid,        t + 1, is32, p1_32, p1_64, p2_32, p2_64);
            px1 = gather_one(states, seq0, tid + 768,  t + 1, is32, p1_32, p1_64, p2_32, p2_64);
            if (tid < SEQPB * 64 - 1536)
                px2 = gather_one(states, seq0, tid + 1536, t + 1, is32, p1_32, p1_64, p2_32, p2_64);
        }

        ull acc[14], acci[14];
        #pragma unroll
        for (int p = 0; p < 14; ++p) { acc[p] = 0ull; acci[p] = 0ull; }

        // ---- recurrent part: chunks 0..63 (K=256), rolling weight prefetch ----
        float4 wcur = Wp4[tid];
        #pragma unroll 2
        for (int c = 0; c < 64; ++c) {
            float4 wnext = Wp4[(c + 1) * 768 + tid];   // c=63 fetches chunk 64 (first x chunk)
            #pragma unroll
            for (int kk = 0; kk < 4; ++kk) {
                float ws = (kk == 0) ? wcur.x : (kk == 1) ? wcur.y : (kk == 2) ? wcur.z : wcur.w;
                ull w2; PACK1(w2, ws);
                const ulonglong2* hp = (const ulonglong2*)(hTf + (4 * c + kk) * 28);
                #pragma unroll
                for (int q = 0; q < 7; ++q) {
                    ulonglong2 hq = hp[q];
                    FFMA2(acc[2 * q],     hq.x, w2);
                    FFMA2(acc[2 * q + 1], hq.y, w2);
                }
            }
            wcur = wnext;
        }
        // ---- input part: chunks 64..79 (K=64), into acci ----
        {
            const float* xb = xTf + cur * 1792;
            #pragma unroll 2
            for (int c2 = 0; c2 < 16; ++c2) {
                const int cn = (c2 < 15) ? (65 + c2) : 79;
                float4 wnext = Wp4[cn * 768 + tid];
                #pragma unroll
                for (int kk = 0; kk < 4; ++kk) {
                    float ws = (kk == 0) ? wcur.x : (kk == 1) ? wcur.y : (kk == 2) ? wcur.z : wcur.w;
                    ull w2; PACK1(w2, ws);
                    const ulonglong2* xp = (const ulonglong2*)(xb + (4 * c2 + kk) * 28);
                    #pragma unroll
                    for (int q = 0; q < 7; ++q) {
                        ulonglong2 xq = xp[q];
                        FFMA2(acci[2 * q],     xq.x, w2);
                        FFMA2(acci[2 * q + 1], xq.y, w2);
                    }
                }
                wcur = wnext;
            }
        }

        // publish prefetched x into other buffer (safe: nobody reads xT[cur^1] now)
        if (t < TSTEP - 1) {
            float* xn = xTf + (cur ^ 1) * 1792;
            xn[(tid & 63) * 28 + (tid >> 6)] = px0;
            {
                int u = tid + 768;
                xn[(u & 63) * 28 + (u >> 6)] = px1;
            }
            if (tid < SEQPB * 64 - 1536) {
                int u = tid + 1536;
                xn[(u & 63) * 28 + (u >> 6)] = px2;
            }
        }

        // r/z gates: activation + store (no sync needed before: rbuf/zbuf not read by mainloop)
        if (g < 2) {
            float* gb = (g == 0) ? rbuf : zbuf;
            #pragma unroll
            for (int p = 0; p < 14; ++p) {
                float a0, a1, x0, x1;
                UNPACK2(a0, a1, acc[p]);
                UNPACK2(x0, x1, acci[p]);
                float v0 = sigm(a0 + x0 + bmain);
                float v1 = sigm(a1 + x1 + bmain);
                ull pk; PACKAB(pk, v0, v1);
                *(ull*)&gb[ch * 30 + 2 * p] = pk;
            }
        }
        __syncthreads();   // A: r,z visible; mainloop reads of hT/xT done

        if (g == 2) {
            #pragma unroll
            for (int p = 0; p < 14; ++p) {
                ull rp = *(const ull*)&rbuf[ch * 30 + 2 * p];
                float r0, r1, nh0, nh1, ni0, ni1;
                UNPACK2(r0, r1, rp);
                UNPACK2(nh0, nh1, acc[p]);
                UNPACK2(ni0, ni1, acci[p]);
                float n0 = tanhf(ni0 + bmain + r0 * (nh0 + bhn));
                float n1 = tanhf(ni1 + bmain + r1 * (nh1 + bhn));
                ull pk; PACKAB(pk, n0, n1);
                *(ull*)&nbuf[ch * 30 + 2 * p] = pk;
            }
        }
        __syncthreads();   // B: n visible

        // cooperative h update: u -> (ch2, si)
        for (int u = tid; u < 7168; u += 768) {
            int ch2 = u / 28, si = u - ch2 * 28;
            float z = zbuf[ch2 * 30 + si];
            float n = nbuf[ch2 * 30 + si];
            float hold = hTf[ch2 * 28 + si];
            float hn = (1.f - z) * n + z * hold;
            hTf[ch2 * 28 + si] = hn;
            if (t == TSTEP - 1) {
                int s = seq0 + si;
                if (s < 4096) {
                    int b, nn, off;
                    if (s < 2048) { b = s >> 6; nn = s & 63; off = 400; }
                    else { int sp = s - 2048; b = sp >> 6; nn = sp & 63; off = 656; }
                    d_f[(size_t)(b * 64 + nn) * INTER + off + ch2] = hn;
                }
            }
        }
        __syncthreads();   // C: hT published for next step
        cur ^= 1;
    }
}

// ---------------- xW1 = f @ Wih1^T + bih1  (M=2048, K=912, N=768) ----------------
__global__ void __launch_bounds__(256) gemm_xw1_kernel(const float* __restrict__ bih1) {
    __shared__ float As[16][64];
    __shared__ float Bs[16][64];
    const int tid = threadIdx.x;
    const int bn = blockIdx.x;     // 0..11
    const int bm = blockIdx.y;     // 0..31
    const int tx = tid & 15, ty = tid >> 4;
    ull acc2[4][2];
    #pragma unroll
    for (int r = 0; r < 4; ++r) { acc2[r][0] = 0ull; acc2[r][1] = 0ull; }

    for (int k0 = 0; k0 < 912; k0 += 16) {
        for (int l = tid; l < 1024; l += 256) {
            int i = l >> 4, k = l & 15;
            As[k][i] = d_f[(size_t)(bm * 64 + i) * INTER + k0 + k];
        }
        for (int l = tid; l < 1024; l += 256) {
            int k = l >> 6, j = l & 63;
            Bs[k][j] = d_WiT1[(size_t)(k0 + k) * 768 + bn * 64 + j];
        }
        __syncthreads();
        #pragma unroll
        for (int k = 0; k < 16; ++k) {
            ulonglong2 bv = *(const ulonglong2*)&Bs[k][tx * 4];
            const float* ap = &As[k][ty * 4];
            #pragma unroll
            for (int r = 0; r < 4; ++r) {
                ull a2;
                PACK1(a2, ap[r]);
                FFMA2(acc2[r][0], a2, bv.x);
                FFMA2(acc2[r][1], a2, bv.y);
            }
        }
        __syncthreads();
    }
    #pragma unroll
    for (int r = 0; r < 4; ++r) {
        int m = bm * 64 + ty * 4 + r;
        int o = bn * 64 + tx * 4;
        float c0, c1, c2, c3;
        UNPACK2(c0, c1, acc2[r][0]);
        UNPACK2(c2, c3, acc2[r][1]);
        float* dst = &d_xW1[(size_t)m * 768 + o];
        dst[0] = c0 + bih1[o];
        dst[1] = c1 + bih1[o + 1];
        dst[2] = c2 + bih1[o + 2];
        dst[3] = c3 + bih1[o + 3];
    }
}

// ---------------- fused 1D GRU: 32 batch rows, duplicated-h f32x2 ----------------
__global__ void __launch_bounds__(384) gru1d_kernel(const float* __restrict__ bhh) {
    __shared__ float2 hd[256];   // h duplicated per slot for direct f32x2 loads
    __shared__ float gh[768];
    const int tid = threadIdx.x;
    const int b = blockIdx.x;
    const float* __restrict__ xW = d_xW1 + (size_t)b * 64 * 768;
    const int o = tid * 2;
    ull bias2;
    PACKAB(bias2, bhh[o], bhh[o + 1]);

    if (tid < 256) hd[tid] = make_float2(0.f, 0.f);
    __syncthreads();

    for (int t = 0; t < TSTEP; ++t) {
        ull acc_a = bias2, acc_b = 0ull;
        #pragma unroll 4
        for (int k = 0; k < 256; k += 2) {
            ull h0 = *(const ull*)&hd[k];
            ull h1 = *(const ull*)&hd[k + 1];
            ull w0 = *(const ull*)&d_WhT1[(size_t)k * 768 + o];
            ull w1 = *(const ull*)&d_WhT1[(size_t)(k + 1) * 768 + o];
            FFMA2(acc_a, h0, w0);
            FFMA2(acc_b, h1, w1);
        }
        ull acc;
        ADD2(acc, acc_a, acc_b);
        *(ull*)&gh[o] = acc;
        __syncthreads();
        if (tid < 256) {
            const float* xwt = xW + t * 768;
            float r = sigm(xwt[tid] + gh[tid]);
            float z = sigm(xwt[256 + tid] + gh[256 + tid]);
            float nn = tanhf(xwt[512 + tid] + r * gh[512 + tid]);
            float hn = (1.f - z) * nn + z * hd[tid].x;
            hd[tid] = make_float2(hn, hn);
        }
        __syncthreads();
    }
    if (tid < 256) d_hlast[b * 256 + tid] = hd[tid].x;
}

// ---------------- final pools over f + fc1 + fc2 ----------------
__global__ void __launch_bounds__(256) final_kernel(const float* __restrict__ fc1b,
                                                    const float* __restrict__ fc2W,
                                                    const float* __restrict__ fc2b,
                                                    float* __restrict__ out) {
    __shared__ float g[2992];
    __shared__ float hh[256];
    __shared__ float red[8];
    const int b = blockIdx.x, tid = threadIdx.x;
    const float* fb = d_f + (size_t)b * 64 * INTER;

    for (int c = tid; c < INTER; c += 256) {
        float mx = -1e30f, mn = 1e30f, sm = 0.f;
        for (int n = 0; n < 64; ++n) {
            float v = fb[n * INTER + c];
            mx = fmaxf(mx, v); mn = fminf(mn, v); sm += v;
        }
        g[c] = mx; g[912 + c] = sm * (1.f / 64.f); g[1824 + c] = mn;
    }
    g[2736 + tid] = d_hlast[b * 256 + tid];
    __syncthreads();

    float acc = fc1b[tid];
    #pragma unroll 4
    for (int j = 0; j < 2992; ++j) acc += g[j] * d_fc1WT[(size_t)j * 256 + tid];
    hh[tid] = fmaxf(acc, 0.f);
    __syncthreads();

    float v = hh[tid] * fc2W[tid];
    #pragma unroll
    for (int off = 16; off > 0; off >>= 1) v += __shfl_down_sync(0xffffffffu, v, off);
    if ((tid & 31) == 0) red[tid >> 5] = v;
    __syncthreads();
    if (tid == 0) {
        float s = 0.f;
        #pragma unroll
        for (int i = 0; i < 8; ++i) s += red[i];
        out[b] = s + fc2b[0];
    }
}

// ---------------- launch ----------------
extern "C" void kernel_launch(void* const* d_in, const int* in_sizes, int n_in,
                              void* d_out, int out_size) {
    const float* x1     = (const float*)d_in[0];
    const float* states = (const float*)d_in[1];
    const void*  perm1  = d_in[2];
    const void*  perm2  = d_in[3];
    const float* Wih2   = (const float*)d_in[4];
    const float* Whh2   = (const float*)d_in[5];
    const float* bih2   = (const float*)d_in[6];
    const float* bhh2   = (const float*)d_in[7];
    const float* Wih1   = (const float*)d_in[8];
    const float* Whh1   = (const float*)d_in[9];
    const float* bih1   = (const float*)d_in[10];
    const float* bhh1   = (const float*)d_in[11];
    const float* fc1W   = (const float*)d_in[12];
    const float* fc1b   = (const float*)d_in[13];
    const float* fc2W   = (const float*)d_in[14];
    const float* fc2b   = (const float*)d_in[15];
    float* out = (float*)d_out;

    static int smem_set = 0;
    if (!smem_set) {
        cudaFuncSetAttribute(gru2d_kernel, cudaFuncAttributeMaxDynamicSharedMemorySize,
                             SM_TOTF * (int)sizeof(float));
        smem_set = 1;
    }

    detect_kernel<<<1, 32>>>((const long long*)perm1);
    prep_kernel<<<7456, 256>>>(Whh2, Wih2, Whh1, Wih1, fc1W);
    pool_kernel<<<1152, 256>>>(states, x1);
    gru2d_kernel<<<NBLK2, 768, SM_TOTF * sizeof(float)>>>(states, perm1, perm2, bih2, bhh2);
    gemm_xw1_kernel<<<dim3(12, 32), 256>>>(bih1);
    gru1d_kernel<<<32, 384>>>(bhh1);
    final_kernel<<<32, 256>>>(fc1b, fc2W, fc2b, out);
}

// round 7
// speedup vs baseline: 1.4124x; 1.4124x over previous
#include <cuda_runtime.h>
#include <cuda_bf16.h>
#include <math.h>

typedef unsigned long long ull;

// Shapes
#define Bsz   32
#define Ndim  64
#define Hdim  256
#define INTER 912      // 2H + 6C + C1
#define TSTEP 64
#define SEQPB 28       // sequences per gru2d block
#define NBLK2 147      // ceil(4096/28) -> one wave on 148 SMs

// f32x2 packed helpers (sm_100+ PTX; ptxas won't auto-fuse)
#define FFMA2(acc, a, b)   asm("fma.rn.f32x2 %0, %1, %2, %0;" : "+l"(acc) : "l"(a), "l"(b))
#define ADD2(d, a, b)      asm("add.rn.f32x2 %0, %1, %2;" : "=l"(d) : "l"(a), "l"(b))
#define PACK1(d, s)        asm("mov.b64 %0, {%1, %1};" : "=l"(d) : "f"(s))
#define PACKAB(d, lo, hi)  asm("mov.b64 %0, {%1, %2};" : "=l"(d) : "f"(lo), "f"(hi))
#define UNPACK2(lo, hi, s) asm("mov.b64 {%0, %1}, %2;" : "=f"(lo), "=f"(hi) : "l"(s))

// ---------------- scratch (device globals; no cudaMalloc allowed) ----------------
__device__ float d_f[Bsz * Ndim * INTER];        // fused feature tensor [B,N,912]
__device__ float d_xW1[Bsz * Ndim * 768];        // precomputed f @ Wih1^T + bih1
__device__ float d_W2p[80 * 768 * 4];            // gru2d packed: [k/4][g*256+o][kk]; chunks 0..63=Whh, 64..79=Wih
__device__ float d_WhT1[256 * 768];              // gru1d Whh transposed [k][o]
__device__ float d_WiT1[912 * 768];              // gru1d Wih transposed
__device__ float d_fc1WT[2992 * 256];            // fc1 W transposed [j][o]
__device__ float d_hlast[Bsz * Hdim];
__device__ int   d_perm_is32;

__device__ __forceinline__ float sigm(float x) { return 1.f / (1.f + __expf(-x)); }

// ---------------- perm dtype probe (int64 vs int32) ----------------
__global__ void detect_kernel(const long long* __restrict__ p) {
    if (threadIdx.x == 0 && blockIdx.x == 0) {
        int is32 = 0;
        for (int i = 0; i < 32; ++i) {
            long long v = p[i];
            if (v < 0 || v >= 64) is32 = 1;   // int32 data read as int64 overflows range
        }
        d_perm_is32 = is32;
    }
}

// ---------------- weight transposes / packing ----------------
__global__ void prep_kernel(const float* __restrict__ Whh2, const float* __restrict__ Wih2,
                            const float* __restrict__ Whh1, const float* __restrict__ Wih1,
                            const float* __restrict__ fc1W) {
    int i = blockIdx.x * blockDim.x + threadIdx.x;
    if (i < 245760) {
        int c = i / 3072;           // chunk stride = 768*4 = 3072 floats
        int rem = i % 3072;
        int o = rem >> 2, kk = rem & 3;   // o = g*256 + out-channel (0..767)
        if (c < 64) d_W2p[i] = Whh2[o * 256 + (4 * c + kk)];
        else        d_W2p[i] = Wih2[o * 64 + (4 * (c - 64) + kk)];
    } else if (i < 442368) {
        int j = i - 245760; int k = j / 768, o = j % 768;
        d_WhT1[j] = Whh1[o * 256 + k];
    } else if (i < 1142784) {
        int j = i - 442368; int k = j / 768, o = j % 768;
        d_WiT1[j] = Wih1[o * 912 + k];
    } else if (i < 1908736) {
        int j = i - 1142784; int o = j % 256, j2 = j / 256;
        d_fc1WT[j] = fc1W[o * 2992 + j2];
    }
}

// ---------------- pools over states + x1 copy into f ----------------
__global__ void pool_kernel(const float* __restrict__ states, const float* __restrict__ x1) {
    int i = blockIdx.x * blockDim.x + threadIdx.x;
    if (i < 131072) {
        int c = i & 63, j = (i >> 6) & 63, b = i >> 12;
        float mx = -1e30f, mn = 1e30f, sm = 0.f;
        for (int n = 0; n < 64; ++n) {
            float v = states[(((b * 64 + n) * 64 + j) << 6) + c];
            mx = fmaxf(mx, v); mn = fminf(mn, v); sm += v;
        }
        float* fp = d_f + (size_t)(b * 64 + j) * INTER;
        fp[16 + c] = mx; fp[80 + c] = sm * (1.f / 64.f); fp[144 + c] = mn;
    } else if (i < 262144) {
        int i2 = i - 131072;
        int c = i2 & 63, n = (i2 >> 6) & 63, b = i2 >> 12;
        float mx = -1e30f, mn = 1e30f, sm = 0.f;
        const float* row = states + (((size_t)(b * 64 + n) * 64) << 6) + c;
        for (int m = 0; m < 64; ++m) {
            float v = row[m << 6];
            mx = fmaxf(mx, v); mn = fminf(mn, v); sm += v;
        }
        float* fp = d_f + (size_t)(b * 64 + n) * INTER;
        fp[208 + c] = mx; fp[272 + c] = sm * (1.f / 64.f); fp[336 + c] = mn;
    } else if (i < 294912) {
        int i3 = i - 262144;
        d_f[(size_t)(i3 >> 4) * INTER + (i3 & 15)] = x1[i3];
    }
}

// ---------------- gather helper for gru2d ----------------
__device__ __forceinline__ float gather_one(const float* __restrict__ states, int seq0, int i, int tt,
        int is32, const int* __restrict__ p1_32, const long long* __restrict__ p1_64,
        const int* __restrict__ p2_32, const long long* __restrict__ p2_64) {
    int si = i >> 6, c = i & 63, s = seq0 + si;
    if (s >= 4096) return 0.f;
    const float* src;
    if (s < 2048) {
        int b = s >> 6, n = s & 63;
        int m = is32 ? p1_32[n * 64 + tt] : (int)p1_64[n * 64 + tt];
        src = states + (((size_t)((b * 64 + n) * 64 + m)) << 6);
    } else {
        int sp = s - 2048;
        int b = sp >> 6, n = sp & 63;
        int sn = is32 ? p2_32[n * 64 + tt] : (int)p2_64[n * 64 + tt];
        src = states + (((size_t)((b * 64 + sn) * 64 + n)) << 6);
    }
    return __ldg(src + c);
}

// SMEM layout (floats):
//   hT   [256][28]        @ 0       (7168)
//   xT   [2][64][28]      @ 7168    (3584)
//   rb   [256][30]        @ 10752   (7680)
//   zb   [256][30]        @ 18432   (7680)
//   nb   [256][30]        @ 26112   (7680)
//   ghn  [256][30]        @ 33792   (7680)   n-gate recurrent spill
#define SM_HT   0
#define SM_XT   7168
#define SM_RB   10752
#define SM_ZB   18432
#define SM_NB   26112
#define SM_GH   33792
#define SM_TOTF 41472

// ---------------- fused 2D GRU: 4096 seqs, 28/block, 147 blocks, 384 threads ----------------
// Thread owns TWO outputs: o0 = tid (always r or z), o1 = tid+384 (z for tid<128, n for tid>=128).
// h/x seq-values are loaded once per k and reused for both outputs (crossbar/fma = 0.5).
__global__ void __launch_bounds__(384, 1) gru2d_kernel(
    const float* __restrict__ states,
    const void* __restrict__ perm1v, const void* __restrict__ perm2v,
    const float* __restrict__ bih, const float* __restrict__ bhh) {
    extern __shared__ float smf[];
    float* hTf  = smf + SM_HT;
    float* xTf  = smf + SM_XT;
    float* rbuf = smf + SM_RB;
    float* zbuf = smf + SM_ZB;
    float* nbuf = smf + SM_NB;
    float* ghnb = smf + SM_GH;

    const int tid  = threadIdx.x;
    const int o0   = tid;
    const int o1   = tid + 384;
    const int ch0  = o0 & 255;
    const int ch1  = o1 & 255;
    const int isz1 = (tid < 128);     // o1 is z gate; else n gate
    const int seq0 = blockIdx.x * SEQPB;
    const int is32 = d_perm_is32;
    const long long* __restrict__ p1_64 = (const long long*)perm1v;
    const long long* __restrict__ p2_64 = (const long long*)perm2v;
    const int* __restrict__ p1_32 = (const int*)perm1v;
    const int* __restrict__ p2_32 = (const int*)perm2v;
    const float4* __restrict__ Wp4 = (const float4*)d_W2p;

    const float bm0  = bih[o0] + bhh[o0];                       // r/z full bias
    const float bm1  = bih[o1] + (isz1 ? bhh[o1] : 0.f);        // z full / n: b_in
    const float bhn1 = bhh[o1];                                  // n: b_hn

    for (int u = tid; u < 7168; u += 384) hTf[u] = 0.f;
    for (int u = tid; u < SEQPB * 64; u += 384) {
        float v = gather_one(states, seq0, u, 0, is32, p1_32, p1_64, p2_32, p2_64);
        xTf[(u & 63) * 28 + (u >> 6)] = v;
    }
    __syncthreads();

    int cur = 0;
    for (int t = 0; t < TSTEP; ++t) {
        // prefetch next step's x (long-latency LDGs covered by mainloop)
        float px0 = 0.f, px1 = 0.f, px2 = 0.f, px3 = 0.f, px4 = 0.f;
        if (t < TSTEP - 1) {
            px0 = gather_one(states, seq0, tid,        t + 1, is32, p1_32, p1_64, p2_32, p2_64);
            px1 = gather_one(states, seq0, tid + 384,  t + 1, is32, p1_32, p1_64, p2_32, p2_64);
            px2 = gather_one(states, seq0, tid + 768,  t + 1, is32, p1_32, p1_64, p2_32, p2_64);
            px3 = gather_one(states, seq0, tid + 1152, t + 1, is32, p1_32, p1_64, p2_32, p2_64);
            if (tid < 256)
                px4 = gather_one(states, seq0, tid + 1536, t + 1, is32, p1_32, p1_64, p2_32, p2_64);
        }

        ull acc0[14], acc1[14];
        #pragma unroll
        for (int p = 0; p < 14; ++p) { acc0[p] = 0ull; acc1[p] = 0ull; }

        // ---- recurrent part: chunks 0..63 (K=256) ----
        float4 w0c = Wp4[o0], w1c = Wp4[o1];
        #pragma unroll 2
        for (int c = 0; c < 64; ++c) {
            float4 w0n = Wp4[(c + 1) * 768 + o0];   // c=63 fetches chunk 64 (first x chunk)
            float4 w1n = Wp4[(c + 1) * 768 + o1];
            const float* hp0 = hTf + 4 * c * 28;
            #pragma unroll
            for (int kk = 0; kk < 4; ++kk) {
                float s0 = (kk == 0) ? w0c.x : (kk == 1) ? w0c.y : (kk == 2) ? w0c.z : w0c.w;
                float s1 = (kk == 0) ? w1c.x : (kk == 1) ? w1c.y : (kk == 2) ? w1c.z : w1c.w;
                ull p0, p1; PACK1(p0, s0); PACK1(p1, s1);
                const ulonglong2* hp = (const ulonglong2*)(hp0 + kk * 28);
                #pragma unroll
                for (int q = 0; q < 7; ++q) {
                    ulonglong2 hq = hp[q];
                    FFMA2(acc0[2 * q],     hq.x, p0);
                    FFMA2(acc0[2 * q + 1], hq.y, p0);
                    FFMA2(acc1[2 * q],     hq.x, p1);
                    FFMA2(acc1[2 * q + 1], hq.y, p1);
                }
            }
            w0c = w0n; w1c = w1n;
        }

        // n-gate threads: spill recurrent partial (gh_n), reuse acc1 for the x-part
        if (!isz1) {
            #pragma unroll
            for (int p = 0; p < 14; ++p) {
                *(ull*)&ghnb[ch1 * 30 + 2 * p] = acc1[p];
                acc1[p] = 0ull;
            }
        }

        // ---- input part: chunks 64..79 (K=64) ----
        {
            const float* xb = xTf + cur * 1792;
            #pragma unroll 2
            for (int c2 = 0; c2 < 16; ++c2) {
                const int cn = (c2 < 15) ? (65 + c2) : 79;
                float4 w0n = Wp4[cn * 768 + o0];
                float4 w1n = Wp4[cn * 768 + o1];
                const float* xp0 = xb + 4 * c2 * 28;
                #pragma unroll
                for (int kk = 0; kk < 4; ++kk) {
                    float s0 = (kk == 0) ? w0c.x : (kk == 1) ? w0c.y : (kk == 2) ? w0c.z : w0c.w;
                    float s1 = (kk == 0) ? w1c.x : (kk == 1) ? w1c.y : (kk == 2) ? w1c.z : w1c.w;
                    ull p0, p1; PACK1(p0, s0); PACK1(p1, s1);
                    const ulonglong2* xp = (const ulonglong2*)(xp0 + kk * 28);
                    #pragma unroll
                    for (int q = 0; q < 7; ++q) {
                        ulonglong2 xq = xp[q];
                        FFMA2(acc0[2 * q],     xq.x, p0);
                        FFMA2(acc0[2 * q + 1], xq.y, p0);
                        FFMA2(acc1[2 * q],     xq.x, p1);
                        FFMA2(acc1[2 * q + 1], xq.y, p1);
                    }
                }
                w0c = w0n; w1c = w1n;
            }
        }

        // publish prefetched x into other buffer (nobody reads xT[cur^1] this step)
        if (t < TSTEP - 1) {
            float* xn = xTf + (cur ^ 1) * 1792;
            int u;
            u = tid;        xn[(u & 63) * 28 + (u >> 6)] = px0;
            u = tid + 384;  xn[(u & 63) * 28 + (u >> 6)] = px1;
            u = tid + 768;  xn[(u & 63) * 28 + (u >> 6)] = px2;
            u = tid + 1152; xn[(u & 63) * 28 + (u >> 6)] = px3;
            if (tid < 256) { u = tid + 1536; xn[(u & 63) * 28 + (u >> 6)] = px4; }
        }

        // o0 (r or z) and o1-if-z: sigmoid + store
        {
            float* gb0 = ((tid < 256) ? rbuf : zbuf) + ch0 * 30;
            #pragma unroll
            for (int p = 0; p < 14; ++p) {
                float a0, a1;
                UNPACK2(a0, a1, acc0[p]);
                float v0 = sigm(a0 + bm0);
                float v1 = sigm(a1 + bm0);
                ull pk; PACKAB(pk, v0, v1);
                *(ull*)&gb0[2 * p] = pk;
            }
            if (isz1) {
                float* gb1 = zbuf + ch1 * 30;
                #pragma unroll
                for (int p = 0; p < 14; ++p) {
                    float a0, a1;
                    UNPACK2(a0, a1, acc1[p]);
                    float v0 = sigm(a0 + bm1);
                    float v1 = sigm(a1 + bm1);
                    ull pk; PACKAB(pk, v0, v1);
                    *(ull*)&gb1[2 * p] = pk;
                }
            }
        }
        __syncthreads();   // A: r,z visible; mainloop reads of hT/xT done

        // n gate: combine x-part (acc1) + spilled recurrent + r
        if (!isz1) {
            #pragma unroll
            for (int p = 0; p < 14; ++p) {
                ull rp = *(const ull*)&rbuf[ch1 * 30 + 2 * p];
                ull gp = *(const ull*)&ghnb[ch1 * 30 + 2 * p];
                float r0, r1, g0, g1, x0, x1;
                UNPACK2(r0, r1, rp);
                UNPACK2(g0, g1, gp);
                UNPACK2(x0, x1, acc1[p]);
                float n0 = tanhf(x0 + bm1 + r0 * (g0 + bhn1));
                float n1 = tanhf(x1 + bm1 + r1 * (g1 + bhn1));
                ull pk; PACKAB(pk, n0, n1);
                *(ull*)&nbuf[ch1 * 30 + 2 * p] = pk;
            }
        }
        __syncthreads();   // B: n visible

        // cooperative h update
        for (int u = tid; u < 7168; u += 384) {
            int ch2 = u / 28, si = u - ch2 * 28;
            float z = zbuf[ch2 * 30 + si];
            float n = nbuf[ch2 * 30 + si];
            float hold = hTf[u];
            float hn = (1.f - z) * n + z * hold;
            hTf[u] = hn;
            if (t == TSTEP - 1) {
                int s = seq0 + si;
                if (s < 4096) {
                    int b, nn, off;
                    if (s < 2048) { b = s >> 6; nn = s & 63; off = 400; }
                    else { int sp = s - 2048; b = sp >> 6; nn = sp & 63; off = 656; }
                    d_f[(size_t)(b * 64 + nn) * INTER + off + ch2] = hn;
                }
            }
        }
        __syncthreads();   // C: hT published for next step
        cur ^= 1;
    }
}

// ---------------- xW1 = f @ Wih1^T + bih1  (M=2048, K=912, N=768) ----------------
__global__ void __launch_bounds__(256) gemm_xw1_kernel(const float* __restrict__ bih1) {
    __shared__ float As[16][64];
    __shared__ float Bs[16][64];
    const int tid = threadIdx.x;
    const int bn = blockIdx.x;     // 0..11
    const int bm = blockIdx.y;     // 0..31
    const int tx = tid & 15, ty = tid >> 4;
    ull acc2[4][2];
    #pragma unroll
    for (int r = 0; r < 4; ++r) { acc2[r][0] = 0ull; acc2[r][1] = 0ull; }

    for (int k0 = 0; k0 < 912; k0 += 16) {
        for (int l = tid; l < 1024; l += 256) {
            int i = l >> 4, k = l & 15;
            As[k][i] = d_f[(size_t)(bm * 64 + i) * INTER + k0 + k];
        }
        for (int l = tid; l < 1024; l += 256) {
            int k = l >> 6, j = l & 63;
            Bs[k][j] = d_WiT1[(size_t)(k0 + k) * 768 + bn * 64 + j];
        }
        __syncthreads();
        #pragma unroll
        for (int k = 0; k < 16; ++k) {
            ulonglong2 bv = *(const ulonglong2*)&Bs[k][tx * 4];
            const float* ap = &As[k][ty * 4];
            #pragma unroll
            for (int r = 0; r < 4; ++r) {
                ull a2;
                PACK1(a2, ap[r]);
                FFMA2(acc2[r][0], a2, bv.x);
                FFMA2(acc2[r][1], a2, bv.y);
            }
        }
        __syncthreads();
    }
    #pragma unroll
    for (int r = 0; r < 4; ++r) {
        int m = bm * 64 + ty * 4 + r;
        int o = bn * 64 + tx * 4;
        float c0, c1, c2, c3;
        UNPACK2(c0, c1, acc2[r][0]);
        UNPACK2(c2, c3, acc2[r][1]);
        float* dst = &d_xW1[(size_t)m * 768 + o];
        dst[0] = c0 + bih1[o];
        dst[1] = c1 + bih1[o + 1];
        dst[2] = c2 + bih1[o + 2];
        dst[3] = c3 + bih1[o + 3];
    }
}

// ---------------- fused 1D GRU: 32 batch rows, k-split + LDG.128 weights ----------------
__global__ void __launch_bounds__(384) gru1d_kernel(const float* __restrict__ bhh) {
    __shared__ float2 hd[256];     // h duplicated per slot for direct f32x2 loads
    __shared__ float ghp[2][768];  // per-k-half partial sums
    const int tid = threadIdx.x;
    const int b = blockIdx.x;
    const float* __restrict__ xW = d_xW1 + (size_t)b * 64 * 768;

    const int kh   = (tid >= 192);
    const int tloc = tid - (kh ? 192 : 0);
    const int o4   = tloc * 4;
    const float* __restrict__ Wbase = d_WhT1 + (size_t)(kh * 128) * 768 + o4;
    const float2* __restrict__ hdh = hd + kh * 128;

    // activation-phase biases (threads < 256 each own one channel)
    float b_r1 = 0.f, b_z1 = 0.f, b_n1 = 0.f;
    if (tid < 256) {
        b_r1 = bhh[tid]; b_z1 = bhh[256 + tid]; b_n1 = bhh[512 + tid];
        hd[tid] = make_float2(0.f, 0.f);
    }
    __syncthreads();

    for (int t = 0; t < TSTEP; ++t) {
        ull a0 = 0ull, a1 = 0ull;
        #pragma unroll 4
        for (int k = 0; k < 128; ++k) {
            ull h2 = *(const ull*)&hdh[k];
            float4 w = *(const float4*)(Wbase + (size_t)k * 768);
            ull wlo, whi;
            PACKAB(wlo, w.x, w.y);
            PACKAB(whi, w.z, w.w);
            FFMA2(a0, h2, wlo);
            FFMA2(a1, h2, whi);
        }
        *(ull*)&ghp[kh][o4]     = a0;
        *(ull*)&ghp[kh][o4 + 2] = a1;
        __syncthreads();
        if (tid < 256) {
            const float* xwt = xW + t * 768;
            float ghr = ghp[0][tid]       + ghp[1][tid]       + b_r1;
            float ghz = ghp[0][256 + tid] + ghp[1][256 + tid] + b_z1;
            float ghn = ghp[0][512 + tid] + ghp[1][512 + tid] + b_n1;
            float r = sigm(xwt[tid] + ghr);
            float z = sigm(xwt[256 + tid] + ghz);
            float nn = tanhf(xwt[512 + tid] + r * ghn);
            float hn = (1.f - z) * nn + z * hd[tid].x;
            hd[tid] = make_float2(hn, hn);
        }
        __syncthreads();
    }
    if (tid < 256) d_hlast[b * 256 + tid] = hd[tid].x;
}

// ---------------- final pools over f + fc1 + fc2 ----------------
__global__ void __launch_bounds__(256) final_kernel(const float* __restrict__ fc1b,
                                                    const float* __restrict__ fc2W,
                                                    const float* __restrict__ fc2b,
                                                    float* __restrict__ out) {
    __shared__ float g[2992];
    __shared__ float hh[256];
    __shared__ float red[8];
    const int b = blockIdx.x, tid = threadIdx.x;
    const float* fb = d_f + (size_t)b * 64 * INTER;

    for (int c = tid; c < INTER; c += 256) {
        float mx = -1e30f, mn = 1e30f, sm = 0.f;
        for (int n = 0; n < 64; ++n) {
            float v = fb[n * INTER + c];
            mx = fmaxf(mx, v); mn = fminf(mn, v); sm += v;
        }
        g[c] = mx; g[912 + c] = sm * (1.f / 64.f); g[1824 + c] = mn;
    }
    g[2736 + tid] = d_hlast[b * 256 + tid];
    __syncthreads();

    float acc = fc1b[tid];
    #pragma unroll 4
    for (int j = 0; j < 2992; ++j) acc += g[j] * d_fc1WT[(size_t)j * 256 + tid];
    hh[tid] = fmaxf(acc, 0.f);
    __syncthreads();

    float v = hh[tid] * fc2W[tid];
    #pragma unroll
    for (int off = 16; off > 0; off >>= 1) v += __shfl_down_sync(0xffffffffu, v, off);
    if ((tid & 31) == 0) red[tid >> 5] = v;
    __syncthreads();
    if (tid == 0) {
        float s = 0.f;
        #pragma unroll
        for (int i = 0; i < 8; ++i) s += red[i];
        out[b] = s + fc2b[0];
    }
}

// ---------------- launch ----------------
extern "C" void kernel_launch(void* const* d_in, const int* in_sizes, int n_in,
                              void* d_out, int out_size) {
    const float* x1     = (const float*)d_in[0];
    const float* states = (const float*)d_in[1];
    const void*  perm1  = d_in[2];
    const void*  perm2  = d_in[3];
    const float* Wih2   = (const float*)d_in[4];
    const float* Whh2   = (const float*)d_in[5];
    const float* bih2   = (const float*)d_in[6];
    const float* bhh2   = (const float*)d_in[7];
    const float* Wih1   = (const float*)d_in[8];
    const float* Whh1   = (const float*)d_in[9];
    const float* bih1   = (const float*)d_in[10];
    const float* bhh1   = (const float*)d_in[11];
    const float* fc1W   = (const float*)d_in[12];
    const float* fc1b   = (const float*)d_in[13];
    const float* fc2W   = (const float*)d_in[14];
    const float* fc2b   = (const float*)d_in[15];
    float* out = (float*)d_out;

    static int smem_set = 0;
    if (!smem_set) {
        cudaFuncSetAttribute(gru2d_kernel, cudaFuncAttributeMaxDynamicSharedMemorySize,
                             SM_TOTF * (int)sizeof(float));
        smem_set = 1;
    }

    detect_kernel<<<1, 32>>>((const long long*)perm1);
    prep_kernel<<<7456, 256>>>(Whh2, Wih2, Whh1, Wih1, fc1W);
    pool_kernel<<<1152, 256>>>(states, x1);
    gru2d_kernel<<<NBLK2, 384, SM_TOTF * sizeof(float)>>>(states, perm1, perm2, bih2, bhh2);
    gemm_xw1_kernel<<<dim3(12, 32), 256>>>(bih1);
    gru1d_kernel<<<32, 384>>>(bhh1);
    final_kernel<<<32, 256>>>(fc1b, fc2W, fc2b, out);
}

// round 9
// speedup vs baseline: 1.4195x; 1.0050x over previous
#include <cuda_runtime.h>
#include <cuda_bf16.h>
#include <math.h>

typedef unsigned long long ull;

// Shapes
#define Bsz   32
#define Ndim  64
#define Hdim  256
#define INTER 912      // 2H + 6C + C1
#define TSTEP 64
#define SEQPB 28       // sequences per gru2d block
#define NBLK2 147      // ceil(4096/28) -> one wave on 148 SMs

// f32x2 packed helpers (sm_100+ PTX; ptxas won't auto-fuse)
#define FFMA2(acc, a, b)   asm("fma.rn.f32x2 %0, %1, %2, %0;" : "+l"(acc) : "l"(a), "l"(b))
#define ADD2(d, a, b)      asm("add.rn.f32x2 %0, %1, %2;" : "=l"(d) : "l"(a), "l"(b))
#define PACK1(d, s)        asm("mov.b64 %0, {%1, %1};" : "=l"(d) : "f"(s))
#define PACKAB(d, lo, hi)  asm("mov.b64 %0, {%1, %2};" : "=l"(d) : "f"(lo), "f"(hi))
#define UNPACK2(lo, hi, s) asm("mov.b64 {%0, %1}, %2;" : "=f"(lo), "=f"(hi) : "l"(s))

// ---------------- scratch (device globals; no cudaMalloc allowed) ----------------
__device__ float d_f[Bsz * Ndim * INTER];        // fused feature tensor [B,N,912]
__device__ float d_xW1[Bsz * Ndim * 768];        // precomputed f @ Wih1^T + bih1
__device__ float d_W2p[80 * 768 * 4];            // gru2d packed: [k/4][g*256+o][kk]; chunks 0..63=Whh, 64..79=Wih
__device__ float d_WhT1[256 * 768];              // gru1d Whh transposed [k][o]
__device__ float d_WiT1[912 * 768];              // gru1d Wih transposed
__device__ float d_fc1WT[2992 * 256];            // fc1 W transposed [j][o]
__device__ float d_hlast[Bsz * Hdim];
__device__ int   d_perm_is32;

__device__ __forceinline__ float sigm(float x) { return 1.f / (1.f + __expf(-x)); }

// ---------------- perm dtype probe (int64 vs int32) ----------------
__global__ void detect_kernel(const long long* __restrict__ p) {
    if (threadIdx.x == 0 && blockIdx.x == 0) {
        int is32 = 0;
        for (int i = 0; i < 32; ++i) {
            long long v = p[i];
            if (v < 0 || v >= 64) is32 = 1;   // int32 data read as int64 overflows range
        }
        d_perm_is32 = is32;
    }
}

// ---------------- weight transposes / packing ----------------
__global__ void prep_kernel(const float* __restrict__ Whh2, const float* __restrict__ Wih2,
                            const float* __restrict__ Whh1, const float* __restrict__ Wih1,
                            const float* __restrict__ fc1W) {
    int i = blockIdx.x * blockDim.x + threadIdx.x;
    if (i < 245760) {
        int c = i / 3072;           // chunk stride = 768*4 = 3072 floats
        int rem = i % 3072;
        int o = rem >> 2, kk = rem & 3;   // o = g*256 + out-channel (0..767)
        if (c < 64) d_W2p[i] = Whh2[o * 256 + (4 * c + kk)];
        else        d_W2p[i] = Wih2[o * 64 + (4 * (c - 64) + kk)];
    } else if (i < 442368) {
        int j = i - 245760; int k = j / 768, o = j % 768;
        d_WhT1[j] = Whh1[o * 256 + k];
    } else if (i < 1142784) {
        int j = i - 442368; int k = j / 768, o = j % 768;
        d_WiT1[j] = Wih1[o * 912 + k];
    } else if (i < 1908736) {
        int j = i - 1142784; int o = j % 256, j2 = j / 256;
        d_fc1WT[j] = fc1W[o * 2992 + j2];
    }
}

// ---------------- pools over states + x1 copy into f ----------------
__global__ void pool_kernel(const float* __restrict__ states, const float* __restrict__ x1) {
    int i = blockIdx.x * blockDim.x + threadIdx.x;
    if (i < 131072) {
        int c = i & 63, j = (i >> 6) & 63, b = i >> 12;
        float mx = -1e30f, mn = 1e30f, sm = 0.f;
        for (int n = 0; n < 64; ++n) {
            float v = states[(((b * 64 + n) * 64 + j) << 6) + c];
            mx = fmaxf(mx, v); mn = fminf(mn, v); sm += v;
        }
        float* fp = d_f + (size_t)(b * 64 + j) * INTER;
        fp[16 + c] = mx; fp[80 + c] = sm * (1.f / 64.f); fp[144 + c] = mn;
    } else if (i < 262144) {
        int i2 = i - 131072;
        int c = i2 & 63, n = (i2 >> 6) & 63, b = i2 >> 12;
        float mx = -1e30f, mn = 1e30f, sm = 0.f;
        const float* row = states + (((size_t)(b * 64 + n) * 64) << 6) + c;
        for (int m = 0; m < 64; ++m) {
            float v = row[m << 6];
            mx = fmaxf(mx, v); mn = fminf(mn, v); sm += v;
        }
        float* fp = d_f + (size_t)(b * 64 + n) * INTER;
        fp[208 + c] = mx; fp[272 + c] = sm * (1.f / 64.f); fp[336 + c] = mn;
    } else if (i < 294912) {
        int i3 = i - 262144;
        d_f[(size_t)(i3 >> 4) * INTER + (i3 & 15)] = x1[i3];
    }
}

// ---------------- gather helper for gru2d ----------------
__device__ __forceinline__ float gather_one(const float* __restrict__ states, int seq0, int i, int tt,
        int is32, const int* __restrict__ p1_32, const long long* __restrict__ p1_64,
        const int* __restrict__ p2_32, const long long* __restrict__ p2_64) {
    int si = i >> 6, c = i & 63, s = seq0 + si;
    if (s >= 4096) return 0.f;
    const float* src;
    if (s < 2048) {
        int b = s >> 6, n = s & 63;
        int m = is32 ? p1_32[n * 64 + tt] : (int)p1_64[n * 64 + tt];
        src = states + (((size_t)((b * 64 + n) * 64 + m)) << 6);
    } else {
        int sp = s - 2048;
        int b = sp >> 6, n = sp & 63;
        int sn = is32 ? p2_32[n * 64 + tt] : (int)p2_64[n * 64 + tt];
        src = states + (((size_t)((b * 64 + sn) * 64 + n)) << 6);
    }
    return __ldg(src + c);
}

// SMEM layout (floats):
//   hT   [256][28]        @ 0       (7168)
//   xT   [2][64][28]      @ 7168    (3584)
//   rb   [256][30]        @ 10752   (7680)
//   zb   [256][30]        @ 18432   (7680)
//   nb   [256][30]        @ 26112   (7680)
//   ghn  [256][30]        @ 33792   (7680)   n-gate recurrent spill
#define SM_HT   0
#define SM_XT   7168
#define SM_RB   10752
#define SM_ZB   18432
#define SM_NB   26112
#define SM_GH   33792
#define SM_TOTF 41472

// ---------------- fused 2D GRU: 4096 seqs, 28/block, 147 blocks, 384 threads ----------------
// Thread owns TWO outputs: o0 = tid (always r or z), o1 = tid+384 (z for tid<128, n for tid>=128).
// h/x seq-values are loaded once per k and reused for both outputs (crossbar/fma = 0.5).
__global__ void __launch_bounds__(384, 1) gru2d_kernel(
    const float* __restrict__ states,
    const void* __restrict__ perm1v, const void* __restrict__ perm2v,
    const float* __restrict__ bih, const float* __restrict__ bhh) {
    extern __shared__ float smf[];
    float* hTf  = smf + SM_HT;
    float* xTf  = smf + SM_XT;
    float* rbuf = smf + SM_RB;
    float* zbuf = smf + SM_ZB;
    float* nbuf = smf + SM_NB;
    float* ghnb = smf + SM_GH;

    const int tid  = threadIdx.x;
    const int o0   = tid;
    const int o1   = tid + 384;
    const int ch0  = o0 & 255;
    const int ch1  = o1 & 255;
    const int isz1 = (tid < 128);     // o1 is z gate; else n gate
    const int seq0 = blockIdx.x * SEQPB;
    const int is32 = d_perm_is32;
    const long long* __restrict__ p1_64 = (const long long*)perm1v;
    const long long* __restrict__ p2_64 = (const long long*)perm2v;
    const int* __restrict__ p1_32 = (const int*)perm1v;
    const int* __restrict__ p2_32 = (const int*)perm2v;
    const float4* __restrict__ Wp4 = (const float4*)d_W2p;

    const float bm0  = bih[o0] + bhh[o0];                       // r/z full bias
    const float bm1  = bih[o1] + (isz1 ? bhh[o1] : 0.f);        // z full / n: b_in
    const float bhn1 = bhh[o1];                                  // n: b_hn

    for (int u = tid; u < 7168; u += 384) hTf[u] = 0.f;
    for (int u = tid; u < SEQPB * 64; u += 384) {
        float v = gather_one(states, seq0, u, 0, is32, p1_32, p1_64, p2_32, p2_64);
        xTf[(u & 63) * 28 + (u >> 6)] = v;
    }
    __syncthreads();

    int cur = 0;
    for (int t = 0; t < TSTEP; ++t) {
        // prefetch next step's x (long-latency LDGs covered by mainloop)
        float px0 = 0.f, px1 = 0.f, px2 = 0.f, px3 = 0.f, px4 = 0.f;
        if (t < TSTEP - 1) {
            px0 = gather_one(states, seq0, tid,        t + 1, is32, p1_32, p1_64, p2_32, p2_64);
            px1 = gather_one(states, seq0, tid + 384,  t + 1, is32, p1_32, p1_64, p2_32, p2_64);
            px2 = gather_one(states, seq0, tid + 768,  t + 1, is32, p1_32, p1_64, p2_32, p2_64);
            px3 = gather_one(states, seq0, tid + 1152, t + 1, is32, p1_32, p1_64, p2_32, p2_64);
            if (tid < 256)
                px4 = gather_one(states, seq0, tid + 1536, t + 1, is32, p1_32, p1_64, p2_32, p2_64);
        }

        ull acc0[14], acc1[14];
        #pragma unroll
        for (int p = 0; p < 14; ++p) { acc0[p] = 0ull; acc1[p] = 0ull; }

        // ---- recurrent part: chunks 0..63 (K=256) ----
        float4 w0c = Wp4[o0], w1c = Wp4[o1];
        #pragma unroll 2
        for (int c = 0; c < 64; ++c) {
            float4 w0n = Wp4[(c + 1) * 768 + o0];   // c=63 fetches chunk 64 (first x chunk)
            float4 w1n = Wp4[(c + 1) * 768 + o1];
            const float* hp0 = hTf + 4 * c * 28;
            #pragma unroll
            for (int kk = 0; kk < 4; ++kk) {
                float s0 = (kk == 0) ? w0c.x : (kk == 1) ? w0c.y : (kk == 2) ? w0c.z : w0c.w;
                float s1 = (kk == 0) ? w1c.x : (kk == 1) ? w1c.y : (kk == 2) ? w1c.z : w1c.w;
                ull p0, p1; PACK1(p0, s0); PACK1(p1, s1);
                const ulonglong2* hp = (const ulonglong2*)(hp0 + kk * 28);
                #pragma unroll
                for (int q = 0; q < 7; ++q) {
                    ulonglong2 hq = hp[q];
                    FFMA2(acc0[2 * q],     hq.x, p0);
                    FFMA2(acc0[2 * q + 1], hq.y, p0);
                    FFMA2(acc1[2 * q],     hq.x, p1);
                    FFMA2(acc1[2 * q + 1], hq.y, p1);
                }
            }
            w0c = w0n; w1c = w1n;
        }

        // n-gate threads: spill recurrent partial (gh_n), reuse acc1 for the x-part
        if (!isz1) {
            #pragma unroll
            for (int p = 0; p < 14; ++p) {
                *(ull*)&ghnb[ch1 * 30 + 2 * p] = acc1[p];
                acc1[p] = 0ull;
            }
        }

        // ---- input part: chunks 64..79 (K=64) ----
        {
            const float* xb = xTf + cur * 1792;
            #pragma unroll 2
            for (int c2 = 0; c2 < 16; ++c2) {
                const int cn = (c2 < 15) ? (65 + c2) : 79;
                float4 w0n = Wp4[cn * 768 + o0];
                float4 w1n = Wp4[cn * 768 + o1];
                const float* xp0 = xb + 4 * c2 * 28;
                #pragma unroll
                for (int kk = 0; kk < 4; ++kk) {
                    float s0 = (kk == 0) ? w0c.x : (kk == 1) ? w0c.y : (kk == 2) ? w0c.z : w0c.w;
                    float s1 = (kk == 0) ? w1c.x : (kk == 1) ? w1c.y : (kk == 2) ? w1c.z : w1c.w;
                    ull p0, p1; PACK1(p0, s0); PACK1(p1, s1);
                    const ulonglong2* xp = (const ulonglong2*)(xp0 + kk * 28);
                    #pragma unroll
                    for (int q = 0; q < 7; ++q) {
                        ulonglong2 xq = xp[q];
                        FFMA2(acc0[2 * q],     xq.x, p0);
                        FFMA2(acc0[2 * q + 1], xq.y, p0);
                        FFMA2(acc1[2 * q],     xq.x, p1);
                        FFMA2(acc1[2 * q + 1], xq.y, p1);
                    }
                }
                w0c = w0n; w1c = w1n;
            }
        }

        // publish prefetched x into other buffer (nobody reads xT[cur^1] this step)
        if (t < TSTEP - 1) {
            float* xn = xTf + (cur ^ 1) * 1792;
            int u;
            u = tid;        xn[(u & 63) * 28 + (u >> 6)] = px0;
            u = tid + 384;  xn[(u & 63) * 28 + (u >> 6)] = px1;
            u = tid + 768;  xn[(u & 63) * 28 + (u >> 6)] = px2;
            u = tid + 1152; xn[(u & 63) * 28 + (u >> 6)] = px3;
            if (tid < 256) { u = tid + 1536; xn[(u & 63) * 28 + (u >> 6)] = px4; }
        }

        // o0 (r or z) and o1-if-z: sigmoid + store
        {
            float* gb0 = ((tid < 256) ? rbuf : zbuf) + ch0 * 30;
            #pragma unroll
            for (int p = 0; p < 14; ++p) {
                float a0, a1;
                UNPACK2(a0, a1, acc0[p]);
                float v0 = sigm(a0 + bm0);
                float v1 = sigm(a1 + bm0);
                ull pk; PACKAB(pk, v0, v1);
                *(ull*)&gb0[2 * p] = pk;
            }
            if (isz1) {
                float* gb1 = zbuf + ch1 * 30;
                #pragma unroll
                for (int p = 0; p < 14; ++p) {
                    float a0, a1;
                    UNPACK2(a0, a1, acc1[p]);
                    float v0 = sigm(a0 + bm1);
                    float v1 = sigm(a1 + bm1);
                    ull pk; PACKAB(pk, v0, v1);
                    *(ull*)&gb1[2 * p] = pk;
                }
            }
        }
        __syncthreads();   // A: r,z visible; mainloop reads of hT/xT done

        // n gate: combine x-part (acc1) + spilled recurrent + r
        if (!isz1) {
            #pragma unroll
            for (int p = 0; p < 14; ++p) {
                ull rp = *(const ull*)&rbuf[ch1 * 30 + 2 * p];
                ull gp = *(const ull*)&ghnb[ch1 * 30 + 2 * p];
                float r0, r1, g0, g1, x0, x1;
                UNPACK2(r0, r1, rp);
                UNPACK2(g0, g1, gp);
                UNPACK2(x0, x1, acc1[p]);
                float n0 = tanhf(x0 + bm1 + r0 * (g0 + bhn1));
                float n1 = tanhf(x1 + bm1 + r1 * (g1 + bhn1));
                ull pk; PACKAB(pk, n0, n1);
                *(ull*)&nbuf[ch1 * 30 + 2 * p] = pk;
            }
        }
        __syncthreads();   // B: n visible

        // cooperative h update
        for (int u = tid; u < 7168; u += 384) {
            int ch2 = u / 28, si = u - ch2 * 28;
            float z = zbuf[ch2 * 30 + si];
            float n = nbuf[ch2 * 30 + si];
            float hold = hTf[u];
            float hn = (1.f - z) * n + z * hold;
            hTf[u] = hn;
            if (t == TSTEP - 1) {
                int s = seq0 + si;
                if (s < 4096) {
                    int b, nn, off;
                    if (s < 2048) { b = s >> 6; nn = s & 63; off = 400; }
                    else { int sp = s - 2048; b = sp >> 6; nn = sp & 63; off = 656; }
                    d_f[(size_t)(b * 64 + nn) * INTER + off + ch2] = hn;
                }
            }
        }
        __syncthreads();   // C: hT published for next step
        cur ^= 1;
    }
}

// ---------------- xW1 = f @ Wih1^T + bih1  (M=2048, K=912, N=768) ----------------
__global__ void __launch_bounds__(256) gemm_xw1_kernel(const float* __restrict__ bih1) {
    __shared__ float As[16][64];
    __shared__ float Bs[16][64];
    const int tid = threadIdx.x;
    const int bn = blockIdx.x;     // 0..11
    const int bm = blockIdx.y;     // 0..31
    const int tx = tid & 15, ty = tid >> 4;
    ull acc2[4][2];
    #pragma unroll
    for (int r = 0; r < 4; ++r) { acc2[r][0] = 0ull; acc2[r][1] = 0ull; }

    for (int k0 = 0; k0 < 912; k0 += 16) {
        for (int l = tid; l < 1024; l += 256) {
            int i = l >> 4, k = l & 15;
            As[k][i] = d_f[(size_t)(bm * 64 + i) * INTER + k0 + k];
        }
        for (int l = tid; l < 1024; l += 256) {
            int k = l >> 6, j = l & 63;
            Bs[k][j] = d_WiT1[(size_t)(k0 + k) * 768 + bn * 64 + j];
        }
        __syncthreads();
        #pragma unroll
        for (int k = 0; k < 16; ++k) {
            ulonglong2 bv = *(const ulonglong2*)&Bs[k][tx * 4];
            const float* ap = &As[k][ty * 4];
            #pragma unroll
            for (int r = 0; r < 4; ++r) {
                ull a2;
                PACK1(a2, ap[r]);
                FFMA2(acc2[r][0], a2, bv.x);
                FFMA2(acc2[r][1], a2, bv.y);
            }
        }
        __syncthreads();
    }
    #pragma unroll
    for (int r = 0; r < 4; ++r) {
        int m = bm * 64 + ty * 4 + r;
        int o = bn * 64 + tx * 4;
        float c0, c1, c2, c3;
        UNPACK2(c0, c1, acc2[r][0]);
        UNPACK2(c2, c3, acc2[r][1]);
        float* dst = &d_xW1[(size_t)m * 768 + o];
        dst[0] = c0 + bih1[o];
        dst[1] = c1 + bih1[o + 1];
        dst[2] = c2 + bih1[o + 2];
        dst[3] = c3 + bih1[o + 3];
    }
}

// ---------------- fused 1D GRU: 32 batch rows, k-split + LDG.128 weights ----------------
__global__ void __launch_bounds__(384) gru1d_kernel(const float* __restrict__ bhh) {
    __shared__ float2 hd[256];     // h duplicated per slot for direct f32x2 loads
    __shared__ float ghp[2][768];  // per-k-half partial sums
    const int tid = threadIdx.x;
    const int b = blockIdx.x;
    const float* __restrict__ xW = d_xW1 + (size_t)b * 64 * 768;

    const int kh   = (tid >= 192);
    const int tloc = tid - (kh ? 192 : 0);
    const int o4   = tloc * 4;
    const float* __restrict__ Wbase = d_WhT1 + (size_t)(kh * 128) * 768 + o4;
    const float2* __restrict__ hdh = hd + kh * 128;

    // activation-phase biases (threads < 256 each own one channel)
    float b_r1 = 0.f, b_z1 = 0.f, b_n1 = 0.f;
    if (tid < 256) {
        b_r1 = bhh[tid]; b_z1 = bhh[256 + tid]; b_n1 = bhh[512 + tid];
        hd[tid] = make_float2(0.f, 0.f);
    }
    __syncthreads();

    for (int t = 0; t < TSTEP; ++t) {
        ull a0 = 0ull, a1 = 0ull;
        #pragma unroll 4
        for (int k = 0; k < 128; ++k) {
            ull h2 = *(const ull*)&hdh[k];
            float4 w = *(const float4*)(Wbase + (size_t)k * 768);
            ull wlo, whi;
            PACKAB(wlo, w.x, w.y);
            PACKAB(whi, w.z, w.w);
            FFMA2(a0, h2, wlo);
            FFMA2(a1, h2, whi);
        }
        *(ull*)&ghp[kh][o4]     = a0;
        *(ull*)&ghp[kh][o4 + 2] = a1;
        __syncthreads();
        if (tid < 256) {
            const float* xwt = xW + t * 768;
            float ghr = ghp[0][tid]       + ghp[1][tid]       + b_r1;
            float ghz = ghp[0][256 + tid] + ghp[1][256 + tid] + b_z1;
            float ghn = ghp[0][512 + tid] + ghp[1][512 + tid] + b_n1;
            float r = sigm(xwt[tid] + ghr);
            float z = sigm(xwt[256 + tid] + ghz);
            float nn = tanhf(xwt[512 + tid] + r * ghn);
            float hn = (1.f - z) * nn + z * hd[tid].x;
            hd[tid] = make_float2(hn, hn);
        }
        __syncthreads();
    }
    if (tid < 256) d_hlast[b * 256 + tid] = hd[tid].x;
}

// ---------------- final pools over f + fc1 + fc2 ----------------
__global__ void __launch_bounds__(256) final_kernel(const float* __restrict__ fc1b,
                                                    const float* __restrict__ fc2W,
                                                    const float* __restrict__ fc2b,
                                                    float* __restrict__ out) {
    __shared__ float g[2992];
    __shared__ float hh[256];
    __shared__ float red[8];
    const int b = blockIdx.x, tid = threadIdx.x;
    const float* fb = d_f + (size_t)b * 64 * INTER;

    for (int c = tid; c < INTER; c += 256) {
        float mx = -1e30f, mn = 1e30f, sm = 0.f;
        for (int n = 0; n < 64; ++n) {
            float v = fb[n * INTER + c];
            mx = fmaxf(mx, v); mn = fminf(mn, v); sm += v;
        }
        g[c] = mx; g[912 + c] = sm * (1.f / 64.f); g[1824 + c] = mn;
    }
    g[2736 + tid] = d_hlast[b * 256 + tid];
    __syncthreads();

    float acc = fc1b[tid];
    #pragma unroll 4
    for (int j = 0; j < 2992; ++j) acc += g[j] * d_fc1WT[(size_t)j * 256 + tid];
    hh[tid] = fmaxf(acc, 0.f);
    __syncthreads();

    float v = hh[tid] * fc2W[tid];
    #pragma unroll
    for (int off = 16; off > 0; off >>= 1) v += __shfl_down_sync(0xffffffffu, v, off);
    if ((tid & 31) == 0) red[tid >> 5] = v;
    __syncthreads();
    if (tid == 0) {
        float s = 0.f;
        #pragma unroll
        for (int i = 0; i < 8; ++i) s += red[i];
        out[b] = s + fc2b[0];
    }
}

// ---------------- launch ----------------
extern "C" void kernel_launch(void* const* d_in, const int* in_sizes, int n_in,
                              void* d_out, int out_size) {
    const float* x1     = (const float*)d_in[0];
    const float* states = (const float*)d_in[1];
    const void*  perm1  = d_in[2];
    const void*  perm2  = d_in[3];
    const float* Wih2   = (const float*)d_in[4];
    const float* Whh2   = (const float*)d_in[5];
    const float* bih2   = (const float*)d_in[6];
    const float* bhh2   = (const float*)d_in[7];
    const float* Wih1   = (const float*)d_in[8];
    const float* Whh1   = (const float*)d_in[9];
    const float* bih1   = (const float*)d_in[10];
    const float* bhh1   = (const float*)d_in[11];
    const float* fc1W   = (const float*)d_in[12];
    const float* fc1b   = (const float*)d_in[13];
    const float* fc2W   = (const float*)d_in[14];
    const float* fc2b   = (const float*)d_in[15];
    float* out = (float*)d_out;

    static int smem_set = 0;
    if (!smem_set) {
        cudaFuncSetAttribute(gru2d_kernel, cudaFuncAttributeMaxDynamicSharedMemorySize,
                             SM_TOTF * (int)sizeof(float));
        smem_set = 1;
    }

    detect_kernel<<<1, 32>>>((const long long*)perm1);
    prep_kernel<<<7456, 256>>>(Whh2, Wih2, Whh1, Wih1, fc1W);
    pool_kernel<<<1152, 256>>>(states, x1);
    gru2d_kernel<<<NBLK2, 384, SM_TOTF * sizeof(float)>>>(states, perm1, perm2, bih2, bhh2);
    gemm_xw1_kernel<<<dim3(12, 32), 256>>>(bih1);
    gru1d_kernel<<<32, 384>>>(bhh1);
    final_kernel<<<32, 256>>>(fc1b, fc2W, fc2b, out);
}

// round 10
// speedup vs baseline: 1.5843x; 1.1162x over previous
#include <cuda_runtime.h>
#include <cuda_bf16.h>
#include <math.h>

typedef unsigned long long ull;

// Shapes
#define Bsz   32
#define Ndim  64
#define Hdim  256
#define INTER 912      // 2H + 6C + C1
#define TSTEP 64
#define SEQPB 14       // sequences per gru2d block
#define NBLK2 293      // ceil(4096/14)

// f32x2 packed helpers (sm_100+ PTX; ptxas won't auto-fuse)
#define FFMA2(acc, a, b)   asm("fma.rn.f32x2 %0, %1, %2, %0;" : "+l"(acc) : "l"(a), "l"(b))
#define ADD2(d, a, b)      asm("add.rn.f32x2 %0, %1, %2;" : "=l"(d) : "l"(a), "l"(b))
#define PACK1(d, s)        asm("mov.b64 %0, {%1, %1};" : "=l"(d) : "f"(s))
#define PACKAB(d, lo, hi)  asm("mov.b64 %0, {%1, %2};" : "=l"(d) : "f"(lo), "f"(hi))
#define UNPACK2(lo, hi, s) asm("mov.b64 {%0, %1}, %2;" : "=f"(lo), "=f"(hi) : "l"(s))

// ---------------- scratch (device globals; no cudaMalloc allowed) ----------------
__device__ float d_f[Bsz * Ndim * INTER];        // fused feature tensor [B,N,912]
__device__ float d_xW1[Bsz * Ndim * 768];        // precomputed f @ Wih1^T + bih1
__device__ float d_W2p[80 * 768 * 4];            // gru2d packed: [k/4][g*256+o][kk]; chunks 0..63=Whh, 64..79=Wih
__device__ float d_WhT1[256 * 768];              // gru1d Whh transposed [k][o]
__device__ float d_WiT1[912 * 768];              // gru1d Wih transposed
__device__ float d_fc1WT[2992 * 256];            // fc1 W transposed [j][o]
__device__ float d_hlast[Bsz * Hdim];
__device__ float d_fc1p[8 * Bsz * 256];          // per-(seg,b) fc1 partial sums
__device__ int   d_perm_is32;

__device__ __forceinline__ float sigm(float x) { return 1.f / (1.f + __expf(-x)); }

// ---------------- perm dtype probe (int64 vs int32) ----------------
__global__ void detect_kernel(const long long* __restrict__ p) {
    if (threadIdx.x == 0 && blockIdx.x == 0) {
        int is32 = 0;
        for (int i = 0; i < 32; ++i) {
            long long v = p[i];
            if (v < 0 || v >= 64) is32 = 1;   // int32 data read as int64 overflows range
        }
        d_perm_is32 = is32;
    }
}

// ---------------- weight transposes / packing ----------------
__global__ void prep_kernel(const float* __restrict__ Whh2, const float* __restrict__ Wih2,
                            const float* __restrict__ Whh1, const float* __restrict__ Wih1,
                            const float* __restrict__ fc1W) {
    int i = blockIdx.x * blockDim.x + threadIdx.x;
    if (i < 245760) {
        int c = i / 3072;           // chunk stride = 768*4 = 3072 floats
        int rem = i % 3072;
        int o = rem >> 2, kk = rem & 3;   // o = g*256 + out-channel (0..767)
        if (c < 64) d_W2p[i] = Whh2[o * 256 + (4 * c + kk)];
        else        d_W2p[i] = Wih2[o * 64 + (4 * (c - 64) + kk)];
    } else if (i < 442368) {
        int j = i - 245760; int k = j / 768, o = j % 768;
        d_WhT1[j] = Whh1[o * 256 + k];
    } else if (i < 1142784) {
        int j = i - 442368; int k = j / 768, o = j % 768;
        d_WiT1[j] = Wih1[o * 912 + k];
    } else if (i < 1908736) {
        int j = i - 1142784; int o = j % 256, j2 = j / 256;
        d_fc1WT[j] = fc1W[o * 2992 + j2];
    }
}

// ---------------- pools over states + x1 copy into f ----------------
__global__ void pool_kernel(const float* __restrict__ states, const float* __restrict__ x1) {
    int i = blockIdx.x * blockDim.x + threadIdx.x;
    if (i < 131072) {
        int c = i & 63, j = (i >> 6) & 63, b = i >> 12;
        float mx = -1e30f, mn = 1e30f, sm = 0.f;
        for (int n = 0; n < 64; ++n) {
            float v = states[(((b * 64 + n) * 64 + j) << 6) + c];
            mx = fmaxf(mx, v); mn = fminf(mn, v); sm += v;
        }
        float* fp = d_f + (size_t)(b * 64 + j) * INTER;
        fp[16 + c] = mx; fp[80 + c] = sm * (1.f / 64.f); fp[144 + c] = mn;
    } else if (i < 262144) {
        int i2 = i - 131072;
        int c = i2 & 63, n = (i2 >> 6) & 63, b = i2 >> 12;
        float mx = -1e30f, mn = 1e30f, sm = 0.f;
        const float* row = states + (((size_t)(b * 64 + n) * 64) << 6) + c;
        for (int m = 0; m < 64; ++m) {
            float v = row[m << 6];
            mx = fmaxf(mx, v); mn = fminf(mn, v); sm += v;
        }
        float* fp = d_f + (size_t)(b * 64 + n) * INTER;
        fp[208 + c] = mx; fp[272 + c] = sm * (1.f / 64.f); fp[336 + c] = mn;
    } else if (i < 294912) {
        int i3 = i - 262144;
        d_f[(size_t)(i3 >> 4) * INTER + (i3 & 15)] = x1[i3];
    }
}

// ---------------- gather helper for gru2d ----------------
__device__ __forceinline__ float gather_one(const float* __restrict__ states, int seq0, int i, int tt,
        int is32, const int* __restrict__ p1_32, const long long* __restrict__ p1_64,
        const int* __restrict__ p2_32, const long long* __restrict__ p2_64) {
    int si = i >> 6, c = i & 63, s = seq0 + si;
    if (s >= 4096) return 0.f;
    const float* src;
    if (s < 2048) {
        int b = s >> 6, n = s & 63;
        int m = is32 ? p1_32[n * 64 + tt] : (int)p1_64[n * 64 + tt];
        src = states + (((size_t)((b * 64 + n) * 64 + m)) << 6);
    } else {
        int sp = s - 2048;
        int b = sp >> 6, n = sp & 63;
        int sn = is32 ? p2_32[n * 64 + tt] : (int)p2_64[n * 64 + tt];
        src = states + (((size_t)((b * 64 + sn) * 64 + n)) << 6);
    }
    return __ldg(src + c);
}

// ---------------- fused 2D GRU (R5-proven): 4096 seqs, 14 per block, 293 blocks ----------------
__global__ void __launch_bounds__(256, 2) gru2d_kernel(
    const float* __restrict__ states,
    const void* __restrict__ perm1v, const void* __restrict__ perm2v,
    const float* __restrict__ bih, const float* __restrict__ bhh) {
    __shared__ float hT[256][16];     // [k][seq] (14 used)
    __shared__ float xT[2][64][16];   // double-buffered gathered x
    const int tid = threadIdx.x;
    const int seq0 = blockIdx.x * SEQPB;
    const int is32 = d_perm_is32;
    const long long* __restrict__ p1_64 = (const long long*)perm1v;
    const long long* __restrict__ p2_64 = (const long long*)perm2v;
    const int* __restrict__ p1_32 = (const int*)perm1v;
    const int* __restrict__ p2_32 = (const int*)perm2v;
    const float4* __restrict__ Wp4 = (const float4*)d_W2p;

    const float b_r  = bih[tid]       + bhh[tid];
    const float b_z  = bih[256 + tid] + bhh[256 + tid];
    const float b_in = bih[512 + tid];
    const float b_hn = bhh[512 + tid];

    for (int i = tid; i < 256 * 16; i += 256) (&hT[0][0])[i] = 0.f;
    // initial gather (t=0) into xT[0]
    for (int i = tid; i < SEQPB * 64; i += 256) {
        float v = gather_one(states, seq0, i, 0, is32, p1_32, p1_64, p2_32, p2_64);
        xT[0][i & 63][i >> 6] = v;
    }
    __syncthreads();

    int cur = 0;
    for (int t = 0; t < TSTEP; ++t) {
        // prefetch next step's x into registers (hidden under compute)
        float px0 = 0.f, px1 = 0.f, px2 = 0.f, px3 = 0.f;
        if (t < TSTEP - 1) {
            px0 = gather_one(states, seq0, tid,       t + 1, is32, p1_32, p1_64, p2_32, p2_64);
            px1 = gather_one(states, seq0, tid + 256, t + 1, is32, p1_32, p1_64, p2_32, p2_64);
            px2 = gather_one(states, seq0, tid + 512, t + 1, is32, p1_32, p1_64, p2_32, p2_64);
            if (tid < SEQPB * 64 - 768)
                px3 = gather_one(states, seq0, tid + 768, t + 1, is32, p1_32, p1_64, p2_32, p2_64);
        }

        ull accr[7], accz[7], accn[7], acci[7];
        #pragma unroll
        for (int p = 0; p < 7; ++p) { accr[p] = 0ull; accz[p] = 0ull; accn[p] = 0ull; acci[p] = 0ull; }

        // recurrent part: chunks 0..63 (K=256), double-buffered weights
        float4 wr = Wp4[tid], wz = Wp4[256 + tid], wn = Wp4[512 + tid];
        #pragma unroll 2
        for (int c = 0; c < 64; ++c) {
            const int cn = c + 1;   // c=63 prefetches chunk 64 (first input chunk)
            float4 nr = Wp4[cn * 768 + tid];
            float4 nz = Wp4[cn * 768 + 256 + tid];
            float4 nn4 = Wp4[cn * 768 + 512 + tid];
            #pragma unroll
            for (int kk = 0; kk < 4; ++kk) {
                const int k = 4 * c + kk;
                const ulonglong2* hp = (const ulonglong2*)&hT[k][0];
                ulonglong2 A = hp[0], Bv = hp[1], Cv = hp[2];
                ull Dv = *(const ull*)&hT[k][12];
                ull hv[7] = {A.x, A.y, Bv.x, Bv.y, Cv.x, Cv.y, Dv};
                float wrs = (kk == 0) ? wr.x : (kk == 1) ? wr.y : (kk == 2) ? wr.z : wr.w;
                float wzs = (kk == 0) ? wz.x : (kk == 1) ? wz.y : (kk == 2) ? wz.z : wz.w;
                float wns = (kk == 0) ? wn.x : (kk == 1) ? wn.y : (kk == 2) ? wn.z : wn.w;
                ull w2r, w2z, w2n;
                PACK1(w2r, wrs); PACK1(w2z, wzs); PACK1(w2n, wns);
                #pragma unroll
                for (int p = 0; p < 7; ++p) {
                    FFMA2(accr[p], hv[p], w2r);
                    FFMA2(accz[p], hv[p], w2z);
                    FFMA2(accn[p], hv[p], w2n);
                }
            }
            wr = nr; wz = nz; wn = nn4;
        }
        // input part: chunks 64..79 (K=64), source xT[cur], n goes to acci
        {
            const float (*xc)[16] = xT[cur];
            #pragma unroll 2
            for (int c2 = 0; c2 < 16; ++c2) {
                const int cn = (c2 < 15) ? (65 + c2) : 79;
                float4 nr = Wp4[cn * 768 + tid];
                float4 nz = Wp4[cn * 768 + 256 + tid];
                float4 nn4 = Wp4[cn * 768 + 512 + tid];
                #pragma unroll
                for (int kk = 0; kk < 4; ++kk) {
                    const int k = 4 * c2 + kk;
                    const ulonglong2* xp = (const ulonglong2*)&xc[k][0];
                    ulonglong2 A = xp[0], Bv = xp[1], Cv = xp[2];
                    ull Dv = *(const ull*)&xc[k][12];
                    ull xv[7] = {A.x, A.y, Bv.x, Bv.y, Cv.x, Cv.y, Dv};
                    float wrs = (kk == 0) ? wr.x : (kk == 1) ? wr.y : (kk == 2) ? wr.z : wr.w;
                    float wzs = (kk == 0) ? wz.x : (kk == 1) ? wz.y : (kk == 2) ? wz.z : wz.w;
                    float wns = (kk == 0) ? wn.x : (kk == 1) ? wn.y : (kk == 2) ? wn.z : wn.w;
                    ull w2r, w2z, w2n;
                    PACK1(w2r, wrs); PACK1(w2z, wzs); PACK1(w2n, wns);
                    #pragma unroll
                    for (int p = 0; p < 7; ++p) {
                        FFMA2(accr[p], xv[p], w2r);
                        FFMA2(accz[p], xv[p], w2z);
                        FFMA2(acci[p], xv[p], w2n);
                    }
                }
                wr = nr; wz = nz; wn = nn4;
            }
        }

        // publish prefetched x into the other buffer
        if (t < TSTEP - 1) {
            float (*xn)[16] = xT[cur ^ 1];
            const int c = tid & 63, si = tid >> 6;
            xn[c][si] = px0;
            xn[c][si + 4] = px1;
            xn[c][si + 8] = px2;
            if (tid < SEQPB * 64 - 768) xn[c][si + 12] = px3;
        }
        __syncthreads();   // compute done reading hT/xT[cur]; next x published

        // epilogue: activations + h update (channel = tid, 14 seqs)
        float4 h4a = *(const float4*)&hT[tid][0];
        float4 h4b = *(const float4*)&hT[tid][4];
        float4 h4c = *(const float4*)&hT[tid][8];
        float2 h2d = *(const float2*)&hT[tid][12];
        float hold[14] = {h4a.x, h4a.y, h4a.z, h4a.w, h4b.x, h4b.y, h4b.z, h4b.w,
                          h4c.x, h4c.y, h4c.z, h4c.w, h2d.x, h2d.y};
        float hnew[14];
        #pragma unroll
        for (int p = 0; p < 7; ++p) {
            float ar0, ar1, az0, az1, ah0, ah1, ai0, ai1;
            UNPACK2(ar0, ar1, accr[p]);
            UNPACK2(az0, az1, accz[p]);
            UNPACK2(ah0, ah1, accn[p]);
            UNPACK2(ai0, ai1, acci[p]);
            float r0 = sigm(ar0 + b_r);
            float z0 = sigm(az0 + b_z);
            float n0 = tanhf(ai0 + b_in + r0 * (ah0 + b_hn));
            hnew[2 * p]     = (1.f - z0) * n0 + z0 * hold[2 * p];
            float r1 = sigm(ar1 + b_r);
            float z1 = sigm(az1 + b_z);
            float n1 = tanhf(ai1 + b_in + r1 * (ah1 + b_hn));
            hnew[2 * p + 1] = (1.f - z1) * n1 + z1 * hold[2 * p + 1];
        }
        *(float4*)&hT[tid][0]  = make_float4(hnew[0], hnew[1], hnew[2], hnew[3]);
        *(float4*)&hT[tid][4]  = make_float4(hnew[4], hnew[5], hnew[6], hnew[7]);
        *(float4*)&hT[tid][8]  = make_float4(hnew[8], hnew[9], hnew[10], hnew[11]);
        *(float2*)&hT[tid][12] = make_float2(hnew[12], hnew[13]);

        if (t == TSTEP - 1) {
            #pragma unroll
            for (int si = 0; si < SEQPB; ++si) {
                int s = seq0 + si;
                if (s < 4096) {
                    int b, n, off;
                    if (s < 2048) { b = s >> 6; n = s & 63; off = 400; }
                    else { int sp = s - 2048; b = sp >> 6; n = sp & 63; off = 656; }
                    d_f[(size_t)(b * 64 + n) * INTER + off + tid] = hnew[si];
                }
            }
        }
        __syncthreads();   // hT published for next step
        cur ^= 1;
    }
}

// ---------------- xW1 = f @ Wih1^T + bih1  (M=2048, K=912, N=768) ----------------
__global__ void __launch_bounds__(256) gemm_xw1_kernel(const float* __restrict__ bih1) {
    __shared__ float As[16][64];
    __shared__ float Bs[16][64];
    const int tid = threadIdx.x;
    const int bn = blockIdx.x;     // 0..11
    const int bm = blockIdx.y;     // 0..31
    const int tx = tid & 15, ty = tid >> 4;
    ull acc2[4][2];
    #pragma unroll
    for (int r = 0; r < 4; ++r) { acc2[r][0] = 0ull; acc2[r][1] = 0ull; }

    for (int k0 = 0; k0 < 912; k0 += 16) {
        for (int l = tid; l < 1024; l += 256) {
            int i = l >> 4, k = l & 15;
            As[k][i] = d_f[(size_t)(bm * 64 + i) * INTER + k0 + k];
        }
        for (int l = tid; l < 1024; l += 256) {
            int k = l >> 6, j = l & 63;
            Bs[k][j] = d_WiT1[(size_t)(k0 + k) * 768 + bn * 64 + j];
        }
        __syncthreads();
        #pragma unroll
        for (int k = 0; k < 16; ++k) {
            ulonglong2 bv = *(const ulonglong2*)&Bs[k][tx * 4];
            const float* ap = &As[k][ty * 4];
            #pragma unroll
            for (int r = 0; r < 4; ++r) {
                ull a2;
                PACK1(a2, ap[r]);
                FFMA2(acc2[r][0], a2, bv.x);
                FFMA2(acc2[r][1], a2, bv.y);
            }
        }
        __syncthreads();
    }
    #pragma unroll
    for (int r = 0; r < 4; ++r) {
        int m = bm * 64 + ty * 4 + r;
        int o = bn * 64 + tx * 4;
        float c0, c1, c2, c3;
        UNPACK2(c0, c1, acc2[r][0]);
        UNPACK2(c2, c3, acc2[r][1]);
        float* dst = &d_xW1[(size_t)m * 768 + o];
        dst[0] = c0 + bih1[o];
        dst[1] = c1 + bih1[o + 1];
        dst[2] = c2 + bih1[o + 2];
        dst[3] = c3 + bih1[o + 3];
    }
}

// ---------------- fused 1D GRU: 32 batch rows, k-split + LDG.128 weights ----------------
__global__ void __launch_bounds__(384) gru1d_kernel(const float* __restrict__ bhh) {
    __shared__ float2 hd[256];     // h duplicated per slot for direct f32x2 loads
    __shared__ float ghp[2][768];  // per-k-half partial sums
    const int tid = threadIdx.x;
    const int b = blockIdx.x;
    const float* __restrict__ xW = d_xW1 + (size_t)b * 64 * 768;

    const int kh   = (tid >= 192);
    const int tloc = tid - (kh ? 192 : 0);
    const int o4   = tloc * 4;
    const float* __restrict__ Wbase = d_WhT1 + (size_t)(kh * 128) * 768 + o4;
    const float2* __restrict__ hdh = hd + kh * 128;

    float b_r1 = 0.f, b_z1 = 0.f, b_n1 = 0.f;
    if (tid < 256) {
        b_r1 = bhh[tid]; b_z1 = bhh[256 + tid]; b_n1 = bhh[512 + tid];
        hd[tid] = make_float2(0.f, 0.f);
    }
    __syncthreads();

    for (int t = 0; t < TSTEP; ++t) {
        ull a0 = 0ull, a1 = 0ull;
        #pragma unroll 4
        for (int k = 0; k < 128; ++k) {
            ull h2 = *(const ull*)&hdh[k];
            float4 w = *(const float4*)(Wbase + (size_t)k * 768);
            ull wlo, whi;
            PACKAB(wlo, w.x, w.y);
            PACKAB(whi, w.z, w.w);
            FFMA2(a0, h2, wlo);
            FFMA2(a1, h2, whi);
        }
        *(ull*)&ghp[kh][o4]     = a0;
        *(ull*)&ghp[kh][o4 + 2] = a1;
        __syncthreads();
        if (tid < 256) {
            const float* xwt = xW + t * 768;
            float ghr = ghp[0][tid]       + ghp[1][tid]       + b_r1;
            float ghz = ghp[0][256 + tid] + ghp[1][256 + tid] + b_z1;
            float ghn = ghp[0][512 + tid] + ghp[1][512 + tid] + b_n1;
            float r = sigm(xwt[tid] + ghr);
            float z = sigm(xwt[256 + tid] + ghz);
            float nn = tanhf(xwt[512 + tid] + r * ghn);
            float hn = (1.f - z) * nn + z * hd[tid].x;
            hd[tid] = make_float2(hn, hn);
        }
        __syncthreads();
    }
    if (tid < 256) d_hlast[b * 256 + tid] = hd[tid].x;
}

// ---------------- fc1 partials: grid (8 segs, 32 b), pool g-chunk + partial dot ----------------
__global__ void __launch_bounds__(256) fc1_partial_kernel() {
    __shared__ float gs[374];
    const int seg = blockIdx.x;      // 0..7
    const int b   = blockIdx.y;      // 0..31
    const int tid = threadIdx.x;
    const int jstart = seg * 374;    // 8*374 = 2992 exactly

    for (int jj = jstart + tid; jj < jstart + 374; jj += 256) {
        float val;
        if (jj < 2736) {
            int kind = jj / 912;             // 0=max, 1=mean, 2=min
            int c = jj - kind * 912;
            const float* fb = d_f + (size_t)b * 64 * INTER + c;
            float mx = -1e30f, mn = 1e30f, sm = 0.f;
            #pragma unroll 4
            for (int n = 0; n < 64; ++n) {
                float v = fb[(size_t)n * INTER];
                mx = fmaxf(mx, v); mn = fminf(mn, v); sm += v;
            }
            val = (kind == 0) ? mx : (kind == 1) ? sm * (1.f / 64.f) : mn;
        } else {
            val = d_hlast[b * 256 + (jj - 2736)];
        }
        gs[jj - jstart] = val;
    }
    __syncthreads();

    float acc = 0.f;
    const float* wt = d_fc1WT + (size_t)jstart * 256 + tid;
    #pragma unroll 4
    for (int u = 0; u < 374; ++u) acc += gs[u] * wt[(size_t)u * 256];
    d_fc1p[((size_t)seg * 32 + b) * 256 + tid] = acc;
}

// ---------------- finish: sum partials, relu, fc2 ----------------
__global__ void __launch_bounds__(256) finish_kernel(const float* __restrict__ fc1b,
                                                     const float* __restrict__ fc2W,
                                                     const float* __restrict__ fc2b,
                                                     float* __restrict__ out) {
    __shared__ float red[8];
    const int b = blockIdx.x, tid = threadIdx.x;
    float s = fc1b[tid];
    #pragma unroll
    for (int seg = 0; seg < 8; ++seg)
        s += d_fc1p[((size_t)seg * 32 + b) * 256 + tid];
    float v = fmaxf(s, 0.f) * fc2W[tid];
    #pragma unroll
    for (int off = 16; off > 0; off >>= 1) v += __shfl_down_sync(0xffffffffu, v, off);
    if ((tid & 31) == 0) red[tid >> 5] = v;
    __syncthreads();
    if (tid == 0) {
        float t = 0.f;
        #pragma unroll
        for (int i = 0; i < 8; ++i) t += red[i];
        out[b] = t + fc2b[0];
    }
}

// ---------------- launch ----------------
extern "C" void kernel_launch(void* const* d_in, const int* in_sizes, int n_in,
                              void* d_out, int out_size) {
    const float* x1     = (const float*)d_in[0];
    const float* states = (const float*)d_in[1];
    const void*  perm1  = d_in[2];
    const void*  perm2  = d_in[3];
    const float* Wih2   = (const float*)d_in[4];
    const float* Whh2   = (const float*)d_in[5];
    const float* bih2   = (const float*)d_in[6];
    const float* bhh2   = (const float*)d_in[7];
    const float* Wih1   = (const float*)d_in[8];
    const float* Whh1   = (const float*)d_in[9];
    const float* bih1   = (const float*)d_in[10];
    const float* bhh1   = (const float*)d_in[11];
    const float* fc1W   = (const float*)d_in[12];
    const float* fc1b   = (const float*)d_in[13];
    const float* fc2W   = (const float*)d_in[14];
    const float* fc2b   = (const float*)d_in[15];
    float* out = (float*)d_out;

    detect_kernel<<<1, 32>>>((const long long*)perm1);
    prep_kernel<<<7456, 256>>>(Whh2, Wih2, Whh1, Wih1, fc1W);
    pool_kernel<<<1152, 256>>>(states, x1);
    gru2d_kernel<<<NBLK2, 256>>>(states, perm1, perm2, bih2, bhh2);
    gemm_xw1_kernel<<<dim3(12, 32), 256>>>(bih1);
    gru1d_kernel<<<32, 384>>>(bhh1);
    fc1_partial_kernel<<<dim3(8, 32), 256>>>();
    finish_kernel<<<32, 256>>>(fc1b, fc2W, fc2b, out);
}

// round 11
// speedup vs baseline: 1.6933x; 1.0688x over previous
#include <cuda_runtime.h>
#include <cuda_bf16.h>
#include <math.h>

typedef unsigned long long ull;

// Shapes
#define Bsz   32
#define Ndim  64
#define Hdim  256
#define INTER 912      // 2H + 6C + C1
#define TSTEP 64
#define SEQPB 14       // sequences per gru2d block
#define NBLK2 293      // ceil(4096/14)

// f32x2 packed helpers (sm_100+ PTX; ptxas won't auto-fuse)
#define FFMA2(acc, a, b)   asm("fma.rn.f32x2 %0, %1, %2, %0;" : "+l"(acc) : "l"(a), "l"(b))
#define ADD2(d, a, b)      asm("add.rn.f32x2 %0, %1, %2;" : "=l"(d) : "l"(a), "l"(b))
#define PACK1(d, s)        asm("mov.b64 %0, {%1, %1};" : "=l"(d) : "f"(s))
#define PACKAB(d, lo, hi)  asm("mov.b64 %0, {%1, %2};" : "=l"(d) : "f"(lo), "f"(hi))
#define UNPACK2(lo, hi, s) asm("mov.b64 {%0, %1}, %2;" : "=f"(lo), "=f"(hi) : "l"(s))

// ---------------- scratch (device globals; no cudaMalloc allowed) ----------------
__device__ float d_f[Bsz * Ndim * INTER];        // fused feature tensor [B,N,912]
__device__ float d_xW1[Bsz * Ndim * 768];        // precomputed f @ Wih1^T + bih1
__device__ float d_W2p[80 * 768 * 4];            // gru2d packed: [k/4][g*256+o][kk]; chunks 0..63=Whh, 64..79=Wih
__device__ float d_WhT1[256 * 768];              // gru1d Whh transposed [k][o]
__device__ float d_WiT1[912 * 768];              // gru1d Wih transposed
__device__ float d_fc1WT[2992 * 256];            // fc1 W transposed [j][o]
__device__ float d_hlast[Bsz * Hdim];
__device__ float d_fc1p[8 * Bsz * 256];          // per-(seg,b) fc1 partial sums
__device__ int   d_perm_is32;

__device__ __forceinline__ float sigm(float x) { return 1.f / (1.f + __expf(-x)); }

// ---------------- weight transposes / packing (+ perm dtype probe folded in) ----------------
__global__ void prep_kernel(const float* __restrict__ Whh2, const float* __restrict__ Wih2,
                            const float* __restrict__ Whh1, const float* __restrict__ Wih1,
                            const float* __restrict__ fc1W, const long long* __restrict__ perm) {
    int i = blockIdx.x * blockDim.x + threadIdx.x;
    if (i == 0) {
        int is32 = 0;
        for (int u = 0; u < 32; ++u) {
            long long v = perm[u];
            if (v < 0 || v >= 64) is32 = 1;   // int32 data read as int64 overflows range
        }
        d_perm_is32 = is32;
    }
    if (i < 245760) {
        int c = i / 3072;           // chunk stride = 768*4 = 3072 floats
        int rem = i % 3072;
        int o = rem >> 2, kk = rem & 3;   // o = g*256 + out-channel (0..767)
        if (c < 64) d_W2p[i] = Whh2[o * 256 + (4 * c + kk)];
        else        d_W2p[i] = Wih2[o * 64 + (4 * (c - 64) + kk)];
    } else if (i < 442368) {
        int j = i - 245760; int k = j / 768, o = j % 768;
        d_WhT1[j] = Whh1[o * 256 + k];
    } else if (i < 1142784) {
        int j = i - 442368; int k = j / 768, o = j % 768;
        d_WiT1[j] = Wih1[o * 912 + k];
    } else if (i < 1908736) {
        int j = i - 1142784; int o = j % 256, j2 = j / 256;
        d_fc1WT[j] = fc1W[o * 2992 + j2];
    }
}

// ---------------- pools over states + x1 copy into f ----------------
__global__ void pool_kernel(const float* __restrict__ states, const float* __restrict__ x1) {
    int i = blockIdx.x * blockDim.x + threadIdx.x;
    if (i < 131072) {
        int c = i & 63, j = (i >> 6) & 63, b = i >> 12;
        float mx = -1e30f, mn = 1e30f, sm = 0.f;
        for (int n = 0; n < 64; ++n) {
            float v = states[(((b * 64 + n) * 64 + j) << 6) + c];
            mx = fmaxf(mx, v); mn = fminf(mn, v); sm += v;
        }
        float* fp = d_f + (size_t)(b * 64 + j) * INTER;
        fp[16 + c] = mx; fp[80 + c] = sm * (1.f / 64.f); fp[144 + c] = mn;
    } else if (i < 262144) {
        int i2 = i - 131072;
        int c = i2 & 63, n = (i2 >> 6) & 63, b = i2 >> 12;
        float mx = -1e30f, mn = 1e30f, sm = 0.f;
        const float* row = states + (((size_t)(b * 64 + n) * 64) << 6) + c;
        for (int m = 0; m < 64; ++m) {
            float v = row[m << 6];
            mx = fmaxf(mx, v); mn = fminf(mn, v); sm += v;
        }
        float* fp = d_f + (size_t)(b * 64 + n) * INTER;
        fp[208 + c] = mx; fp[272 + c] = sm * (1.f / 64.f); fp[336 + c] = mn;
    } else if (i < 294912) {
        int i3 = i - 262144;
        d_f[(size_t)(i3 >> 4) * INTER + (i3 & 15)] = x1[i3];
    }
}

// ---------------- gather helper for gru2d ----------------
__device__ __forceinline__ float gather_one(const float* __restrict__ states, int seq0, int i, int tt,
        int is32, const int* __restrict__ p1_32, const long long* __restrict__ p1_64,
        const int* __restrict__ p2_32, const long long* __restrict__ p2_64) {
    int si = i >> 6, c = i & 63, s = seq0 + si;
    if (s >= 4096) return 0.f;
    const float* src;
    if (s < 2048) {
        int b = s >> 6, n = s & 63;
        int m = is32 ? p1_32[n * 64 + tt] : (int)p1_64[n * 64 + tt];
        src = states + (((size_t)((b * 64 + n) * 64 + m)) << 6);
    } else {
        int sp = s - 2048;
        int b = sp >> 6, n = sp & 63;
        int sn = is32 ? p2_32[n * 64 + tt] : (int)p2_64[n * 64 + tt];
        src = states + (((size_t)((b * 64 + sn) * 64 + n)) << 6);
    }
    return __ldg(src + c);
}

// ---------------- fused 2D GRU (R5-proven, frozen): 4096 seqs, 14 per block ----------------
__global__ void __launch_bounds__(256, 2) gru2d_kernel(
    const float* __restrict__ states,
    const void* __restrict__ perm1v, const void* __restrict__ perm2v,
    const float* __restrict__ bih, const float* __restrict__ bhh) {
    __shared__ float hT[256][16];     // [k][seq] (14 used)
    __shared__ float xT[2][64][16];   // double-buffered gathered x
    const int tid = threadIdx.x;
    const int seq0 = blockIdx.x * SEQPB;
    const int is32 = d_perm_is32;
    const long long* __restrict__ p1_64 = (const long long*)perm1v;
    const long long* __restrict__ p2_64 = (const long long*)perm2v;
    const int* __restrict__ p1_32 = (const int*)perm1v;
    const int* __restrict__ p2_32 = (const int*)perm2v;
    const float4* __restrict__ Wp4 = (const float4*)d_W2p;

    const float b_r  = bih[tid]       + bhh[tid];
    const float b_z  = bih[256 + tid] + bhh[256 + tid];
    const float b_in = bih[512 + tid];
    const float b_hn = bhh[512 + tid];

    for (int i = tid; i < 256 * 16; i += 256) (&hT[0][0])[i] = 0.f;
    for (int i = tid; i < SEQPB * 64; i += 256) {
        float v = gather_one(states, seq0, i, 0, is32, p1_32, p1_64, p2_32, p2_64);
        xT[0][i & 63][i >> 6] = v;
    }
    __syncthreads();

    int cur = 0;
    for (int t = 0; t < TSTEP; ++t) {
        float px0 = 0.f, px1 = 0.f, px2 = 0.f, px3 = 0.f;
        if (t < TSTEP - 1) {
            px0 = gather_one(states, seq0, tid,       t + 1, is32, p1_32, p1_64, p2_32, p2_64);
            px1 = gather_one(states, seq0, tid + 256, t + 1, is32, p1_32, p1_64, p2_32, p2_64);
            px2 = gather_one(states, seq0, tid + 512, t + 1, is32, p1_32, p1_64, p2_32, p2_64);
            if (tid < SEQPB * 64 - 768)
                px3 = gather_one(states, seq0, tid + 768, t + 1, is32, p1_32, p1_64, p2_32, p2_64);
        }

        ull accr[7], accz[7], accn[7], acci[7];
        #pragma unroll
        for (int p = 0; p < 7; ++p) { accr[p] = 0ull; accz[p] = 0ull; accn[p] = 0ull; acci[p] = 0ull; }

        // recurrent part: chunks 0..63 (K=256), double-buffered weights
        float4 wr = Wp4[tid], wz = Wp4[256 + tid], wn = Wp4[512 + tid];
        #pragma unroll 2
        for (int c = 0; c < 64; ++c) {
            const int cn = c + 1;   // c=63 prefetches chunk 64 (first input chunk)
            float4 nr = Wp4[cn * 768 + tid];
            float4 nz = Wp4[cn * 768 + 256 + tid];
            float4 nn4 = Wp4[cn * 768 + 512 + tid];
            #pragma unroll
            for (int kk = 0; kk < 4; ++kk) {
                const int k = 4 * c + kk;
                const ulonglong2* hp = (const ulonglong2*)&hT[k][0];
                ulonglong2 A = hp[0], Bv = hp[1], Cv = hp[2];
                ull Dv = *(const ull*)&hT[k][12];
                ull hv[7] = {A.x, A.y, Bv.x, Bv.y, Cv.x, Cv.y, Dv};
                float wrs = (kk == 0) ? wr.x : (kk == 1) ? wr.y : (kk == 2) ? wr.z : wr.w;
                float wzs = (kk == 0) ? wz.x : (kk == 1) ? wz.y : (kk == 2) ? wz.z : wz.w;
                float wns = (kk == 0) ? wn.x : (kk == 1) ? wn.y : (kk == 2) ? wn.z : wn.w;
                ull w2r, w2z, w2n;
                PACK1(w2r, wrs); PACK1(w2z, wzs); PACK1(w2n, wns);
                #pragma unroll
                for (int p = 0; p < 7; ++p) {
                    FFMA2(accr[p], hv[p], w2r);
                    FFMA2(accz[p], hv[p], w2z);
                    FFMA2(accn[p], hv[p], w2n);
                }
            }
            wr = nr; wz = nz; wn = nn4;
        }
        // input part: chunks 64..79 (K=64), source xT[cur], n goes to acci
        {
            const float (*xc)[16] = xT[cur];
            #pragma unroll 2
            for (int c2 = 0; c2 < 16; ++c2) {
                const int cn = (c2 < 15) ? (65 + c2) : 79;
                float4 nr = Wp4[cn * 768 + tid];
                float4 nz = Wp4[cn * 768 + 256 + tid];
                float4 nn4 = Wp4[cn * 768 + 512 + tid];
                #pragma unroll
                for (int kk = 0; kk < 4; ++kk) {
                    const int k = 4 * c2 + kk;
                    const ulonglong2* xp = (const ulonglong2*)&xc[k][0];
                    ulonglong2 A = xp[0], Bv = xp[1], Cv = xp[2];
                    ull Dv = *(const ull*)&xc[k][12];
                    ull xv[7] = {A.x, A.y, Bv.x, Bv.y, Cv.x, Cv.y, Dv};
                    float wrs = (kk == 0) ? wr.x : (kk == 1) ? wr.y : (kk == 2) ? wr.z : wr.w;
                    float wzs = (kk == 0) ? wz.x : (kk == 1) ? wz.y : (kk == 2) ? wz.z : wz.w;
                    float wns = (kk == 0) ? wn.x : (kk == 1) ? wn.y : (kk == 2) ? wn.z : wn.w;
                    ull w2r, w2z, w2n;
                    PACK1(w2r, wrs); PACK1(w2z, wzs); PACK1(w2n, wns);
                    #pragma unroll
                    for (int p = 0; p < 7; ++p) {
                        FFMA2(accr[p], xv[p], w2r);
                        FFMA2(accz[p], xv[p], w2z);
                        FFMA2(acci[p], xv[p], w2n);
                    }
                }
                wr = nr; wz = nz; wn = nn4;
            }
        }

        // publish prefetched x into the other buffer
        if (t < TSTEP - 1) {
            float (*xn)[16] = xT[cur ^ 1];
            const int c = tid & 63, si = tid >> 6;
            xn[c][si] = px0;
            xn[c][si + 4] = px1;
            xn[c][si + 8] = px2;
            if (tid < SEQPB * 64 - 768) xn[c][si + 12] = px3;
        }
        __syncthreads();

        float4 h4a = *(const float4*)&hT[tid][0];
        float4 h4b = *(const float4*)&hT[tid][4];
        float4 h4c = *(const float4*)&hT[tid][8];
        float2 h2d = *(const float2*)&hT[tid][12];
        float hold[14] = {h4a.x, h4a.y, h4a.z, h4a.w, h4b.x, h4b.y, h4b.z, h4b.w,
                          h4c.x, h4c.y, h4c.z, h4c.w, h2d.x, h2d.y};
        float hnew[14];
        #pragma unroll
        for (int p = 0; p < 7; ++p) {
            float ar0, ar1, az0, az1, ah0, ah1, ai0, ai1;
            UNPACK2(ar0, ar1, accr[p]);
            UNPACK2(az0, az1, accz[p]);
            UNPACK2(ah0, ah1, accn[p]);
            UNPACK2(ai0, ai1, acci[p]);
            float r0 = sigm(ar0 + b_r);
            float z0 = sigm(az0 + b_z);
            float n0 = tanhf(ai0 + b_in + r0 * (ah0 + b_hn));
            hnew[2 * p]     = (1.f - z0) * n0 + z0 * hold[2 * p];
            float r1 = sigm(ar1 + b_r);
            float z1 = sigm(az1 + b_z);
            float n1 = tanhf(ai1 + b_in + r1 * (ah1 + b_hn));
            hnew[2 * p + 1] = (1.f - z1) * n1 + z1 * hold[2 * p + 1];
        }
        *(float4*)&hT[tid][0]  = make_float4(hnew[0], hnew[1], hnew[2], hnew[3]);
        *(float4*)&hT[tid][4]  = make_float4(hnew[4], hnew[5], hnew[6], hnew[7]);
        *(float4*)&hT[tid][8]  = make_float4(hnew[8], hnew[9], hnew[10], hnew[11]);
        *(float2*)&hT[tid][12] = make_float2(hnew[12], hnew[13]);

        if (t == TSTEP - 1) {
            #pragma unroll
            for (int si = 0; si < SEQPB; ++si) {
                int s = seq0 + si;
                if (s < 4096) {
                    int b, n, off;
                    if (s < 2048) { b = s >> 6; n = s & 63; off = 400; }
                    else { int sp = s - 2048; b = sp >> 6; n = sp & 63; off = 656; }
                    d_f[(size_t)(b * 64 + n) * INTER + off + tid] = hnew[si];
                }
            }
        }
        __syncthreads();
        cur ^= 1;
    }
}

// ---------------- xW1 = f @ Wih1^T + bih1  (M=2048, K=912, N=768), reg double-buffered ----------------
__global__ void __launch_bounds__(256) gemm_xw1_kernel(const float* __restrict__ bih1) {
    __shared__ float As[16][64];
    __shared__ float Bs[16][64];
    const int tid = threadIdx.x;
    const int bn = blockIdx.x;     // 0..11
    const int bm = blockIdx.y;     // 0..31
    const int tx = tid & 15, ty = tid >> 4;
    // staging indices: A: thread -> row ai, 4 k's at aq; B: row bk, 4 j's at bq
    const int ai = tid >> 2, aq = (tid & 3) * 4;
    const int bk = tid >> 4, bq = (tid & 15) * 4;
    const float* __restrict__ Arow = d_f + (size_t)(bm * 64 + ai) * INTER + aq;
    const float* __restrict__ Brow = d_WiT1 + (size_t)bk * 768 + bn * 64 + bq;

    ull acc2[4][2];
    #pragma unroll
    for (int r = 0; r < 4; ++r) { acc2[r][0] = 0ull; acc2[r][1] = 0ull; }

    float4 pa = *(const float4*)Arow;
    float4 pb = *(const float4*)Brow;

    #pragma unroll 1
    for (int kt = 0; kt < 57; ++kt) {
        // publish staged tile
        As[aq + 0][ai] = pa.x;
        As[aq + 1][ai] = pa.y;
        As[aq + 2][ai] = pa.z;
        As[aq + 3][ai] = pa.w;
        *(float4*)&Bs[bk][bq] = pb;
        __syncthreads();
        // prefetch next tile while computing this one
        if (kt < 56) {
            pa = *(const float4*)(Arow + (kt + 1) * 16);
            pb = *(const float4*)(Brow + (size_t)(kt + 1) * 16 * 768);
        }
        #pragma unroll
        for (int k = 0; k < 16; ++k) {
            ulonglong2 bv = *(const ulonglong2*)&Bs[k][tx * 4];
            const float* ap = &As[k][ty * 4];
            #pragma unroll
            for (int r = 0; r < 4; ++r) {
                ull a2;
                PACK1(a2, ap[r]);
                FFMA2(acc2[r][0], a2, bv.x);
                FFMA2(acc2[r][1], a2, bv.y);
            }
        }
        __syncthreads();
    }
    #pragma unroll
    for (int r = 0; r < 4; ++r) {
        int m = bm * 64 + ty * 4 + r;
        int o = bn * 64 + tx * 4;
        float c0, c1, c2, c3;
        UNPACK2(c0, c1, acc2[r][0]);
        UNPACK2(c2, c3, acc2[r][1]);
        float* dst = &d_xW1[(size_t)m * 768 + o];
        dst[0] = c0 + bih1[o];
        dst[1] = c1 + bih1[o + 1];
        dst[2] = c2 + bih1[o + 2];
        dst[3] = c3 + bih1[o + 3];
    }
}

// ---------------- fused 1D GRU: 32 batch rows, k-split, direct ull2 weight loads ----------------
__global__ void __launch_bounds__(384) gru1d_kernel(const float* __restrict__ bhh) {
    __shared__ float2 hd[256];     // h duplicated per slot for direct f32x2 loads
    __shared__ float ghp[2][768];  // per-k-half partial sums
    const int tid = threadIdx.x;
    const int b = blockIdx.x;
    const float* __restrict__ xW = d_xW1 + (size_t)b * 64 * 768;

    const int kh   = (tid >= 192);
    const int tloc = tid - (kh ? 192 : 0);
    const int o4   = tloc * 4;
    const float* __restrict__ Wbase = d_WhT1 + (size_t)(kh * 128) * 768 + o4;
    const float2* __restrict__ hdh = hd + kh * 128;

    float b_r1 = 0.f, b_z1 = 0.f, b_n1 = 0.f;
    if (tid < 256) {
        b_r1 = bhh[tid]; b_z1 = bhh[256 + tid]; b_n1 = bhh[512 + tid];
        hd[tid] = make_float2(0.f, 0.f);
    }
    __syncthreads();

    for (int t = 0; t < TSTEP; ++t) {
        ull a0 = 0ull, a1 = 0ull;
        #pragma unroll 8
        for (int k = 0; k < 128; ++k) {
            ull h2 = *(const ull*)&hdh[k];
            ulonglong2 w2 = *(const ulonglong2*)(Wbase + (size_t)k * 768);
            FFMA2(a0, h2, w2.x);
            FFMA2(a1, h2, w2.y);
        }
        *(ull*)&ghp[kh][o4]     = a0;
        *(ull*)&ghp[kh][o4 + 2] = a1;
        __syncthreads();
        if (tid < 256) {
            const float* xwt = xW + t * 768;
            float ghr = ghp[0][tid]       + ghp[1][tid]       + b_r1;
            float ghz = ghp[0][256 + tid] + ghp[1][256 + tid] + b_z1;
            float ghn = ghp[0][512 + tid] + ghp[1][512 + tid] + b_n1;
            float r = sigm(xwt[tid] + ghr);
            float z = sigm(xwt[256 + tid] + ghz);
            float nn = tanhf(xwt[512 + tid] + r * ghn);
            float hn = (1.f - z) * nn + z * hd[tid].x;
            hd[tid] = make_float2(hn, hn);
        }
        __syncthreads();
    }
    if (tid < 256) d_hlast[b * 256 + tid] = hd[tid].x;
}

// ---------------- fc1 partials: grid (8 segs, 32 b), pool g-chunk + partial dot ----------------
__global__ void __launch_bounds__(256) fc1_partial_kernel() {
    __shared__ float gs[374];
    const int seg = blockIdx.x;      // 0..7
    const int b   = blockIdx.y;      // 0..31
    const int tid = threadIdx.x;
    const int jstart = seg * 374;    // 8*374 = 2992 exactly

    for (int jj = jstart + tid; jj < jstart + 374; jj += 256) {
        float val;
        if (jj < 2736) {
            int kind = jj / 912;             // 0=max, 1=mean, 2=min
            int c = jj - kind * 912;
            const float* fb = d_f + (size_t)b * 64 * INTER + c;
            float mx = -1e30f, mn = 1e30f, sm = 0.f;
            #pragma unroll 4
            for (int n = 0; n < 64; ++n) {
                float v = fb[(size_t)n * INTER];
                mx = fmaxf(mx, v); mn = fminf(mn, v); sm += v;
            }
            val = (kind == 0) ? mx : (kind == 1) ? sm * (1.f / 64.f) : mn;
        } else {
            val = d_hlast[b * 256 + (jj - 2736)];
        }
        gs[jj - jstart] = val;
    }
    __syncthreads();

    float acc = 0.f;
    const float* wt = d_fc1WT + (size_t)jstart * 256 + tid;
    #pragma unroll 4
    for (int u = 0; u < 374; ++u) acc += gs[u] * wt[(size_t)u * 256];
    d_fc1p[((size_t)seg * 32 + b) * 256 + tid] = acc;
}

// ---------------- finish: sum partials, relu, fc2 ----------------
__global__ void __launch_bounds__(256) finish_kernel(const float* __restrict__ fc1b,
                                                     const float* __restrict__ fc2W,
                                                     const float* __restrict__ fc2b,
                                                     float* __restrict__ out) {
    __shared__ float red[8];
    const int b = blockIdx.x, tid = threadIdx.x;
    float s = fc1b[tid];
    #pragma unroll
    for (int seg = 0; seg < 8; ++seg)
        s += d_fc1p[((size_t)seg * 32 + b) * 256 + tid];
    float v = fmaxf(s, 0.f) * fc2W[tid];
    #pragma unroll
    for (int off = 16; off > 0; off >>= 1) v += __shfl_down_sync(0xffffffffu, v, off);
    if ((tid & 31) == 0) red[tid >> 5] = v;
    __syncthreads();
    if (tid == 0) {
        float t = 0.f;
        #pragma unroll
        for (int i = 0; i < 8; ++i) t += red[i];
        out[b] = t + fc2b[0];
    }
}

// ---------------- launch ----------------
extern "C" void kernel_launch(void* const* d_in, const int* in_sizes, int n_in,
                              void* d_out, int out_size) {
    const float* x1     = (const float*)d_in[0];
    const float* states = (const float*)d_in[1];
    const void*  perm1  = d_in[2];
    const void*  perm2  = d_in[3];
    const float* Wih2   = (const float*)d_in[4];
    const float* Whh2   = (const float*)d_in[5];
    const float* bih2   = (const float*)d_in[6];
    const float* bhh2   = (const float*)d_in[7];
    const float* Wih1   = (const float*)d_in[8];
    const float* Whh1   = (const float*)d_in[9];
    const float* bih1   = (const float*)d_in[10];
    const float* bhh1   = (const float*)d_in[11];
    const float* fc1W   = (const float*)d_in[12];
    const float* fc1b   = (const float*)d_in[13];
    const float* fc2W   = (const float*)d_in[14];
    const float* fc2b   = (const float*)d_in[15];
    float* out = (float*)d_out;

    prep_kernel<<<7456, 256>>>(Whh2, Wih2, Whh1, Wih1, fc1W, (const long long*)perm1);
    pool_kernel<<<1152, 256>>>(states, x1);
    gru2d_kernel<<<NBLK2, 256>>>(states, perm1, perm2, bih2, bhh2);
    gemm_xw1_kernel<<<dim3(12, 32), 256>>>(bih1);
    gru1d_kernel<<<32, 384>>>(bhh1);
    fc1_partial_kernel<<<dim3(8, 32), 256>>>();
    finish_kernel<<<32, 256>>>(fc1b, fc2W, fc2b, out);
}